// round 14
// baseline (speedup 1.0000x reference)
#include <cuda_runtime.h>
#include <cuda_fp16.h>

#define BB 2
#define SS 2048
#define DD 1024
#define HH 16
#define DKK 64
#define KSPLIT 32

// ---------------- device scratch ----------------
__device__ __align__(16) __half g_qh [(size_t)BB*SS*DD];
__device__ __align__(16) __half g_kh [(size_t)BB*SS*DD];
__device__ __align__(16) __half g_vh [(size_t)BB*SS*DD];
__device__ __align__(16) __half g_wqh[(size_t)HH*DD*DKK];
__device__ __align__(16) __half g_wkh[(size_t)HH*DD*DKK];
__device__ __align__(16) __half g_wvh[(size_t)DD*DKK];
__device__ __align__(16) __half g_qs [(size_t)BB*HH*SS*DKK];  // fp16 Q proj, scaled log2e/8
__device__ __align__(16) __half g_ks [(size_t)BB*HH*SS*DKK];  // fp16 K proj
__device__ __align__(16) __half g_vsh[(size_t)BB*SS*DKK];     // fp16 V proj
__device__ float g_w [(size_t)BB*HH*SS];                       // 1/(H * rowsum)
__device__ float g_headp[(size_t)KSPLIT*BB*SS*DKK];            // per-t-tile PV partials
__device__ float g_head [(size_t)BB*SS*DKK];

// ---------------- helpers ----------------
__device__ __forceinline__ __half2 h2ex2(__half2 x){
    unsigned xi = *reinterpret_cast<unsigned*>(&x), yi;
    asm("ex2.approx.f16x2 %0, %1;" : "=r"(yi) : "r"(xi));
    return *reinterpret_cast<__half2*>(&yi);
}
__device__ __forceinline__ void mma16816(float c[4], const unsigned a[4], const unsigned b[2]) {
    asm volatile("mma.sync.aligned.m16n8k16.row.col.f32.f16.f16.f32 "
        "{%0,%1,%2,%3},{%4,%5,%6,%7},{%8,%9},{%0,%1,%2,%3};\n"
        : "+f"(c[0]),"+f"(c[1]),"+f"(c[2]),"+f"(c[3])
        : "r"(a[0]),"r"(a[1]),"r"(a[2]),"r"(a[3]),"r"(b[0]),"r"(b[1]));
}
__device__ __forceinline__ void mma16816h(unsigned c[2], const unsigned a[4], const unsigned b[2]) {
    asm volatile("mma.sync.aligned.m16n8k16.row.col.f16.f16.f16.f16 "
        "{%0,%1},{%2,%3,%4,%5},{%6,%7},{%0,%1};\n"
        : "+r"(c[0]),"+r"(c[1])
        : "r"(a[0]),"r"(a[1]),"r"(a[2]),"r"(a[3]),"r"(b[0]),"r"(b[1]));
}
__device__ __forceinline__ void ldsm4(unsigned r[4], unsigned a) {
    asm volatile("ldmatrix.sync.aligned.m8n8.x4.shared.b16 {%0,%1,%2,%3}, [%4];"
        : "=r"(r[0]),"=r"(r[1]),"=r"(r[2]),"=r"(r[3]) : "r"(a));
}
__device__ __forceinline__ void ldsm4t(unsigned r[4], unsigned a) {
    asm volatile("ldmatrix.sync.aligned.m8n8.x4.trans.shared.b16 {%0,%1,%2,%3}, [%4];"
        : "=r"(r[0]),"=r"(r[1]),"=r"(r[2]),"=r"(r[3]) : "r"(a));
}
__device__ __forceinline__ void cp16(void* dst, const void* src) {
    unsigned d = (unsigned)__cvta_generic_to_shared(dst);
    asm volatile("cp.async.ca.shared.global [%0], [%1], 16;\n" :: "r"(d), "l"(src));
}
#define CP_COMMIT() asm volatile("cp.async.commit_group;\n")
#define CP_WAIT(N)  asm volatile("cp.async.wait_group %0;\n" :: "n"(N))

// ================= K0: fused fp32 -> fp16 conversions =================
__global__ void k_cvt_all(const float* __restrict__ q, const float* __restrict__ k,
                          const float* __restrict__ v, const float* __restrict__ Wq,
                          const float* __restrict__ Wk, const float* __restrict__ Wv) {
    const int NA = BB*SS*DD/2;
    const int NW = HH*DD*DKK/2;
    const int NWV = DD*DKK/2;
    int i = blockIdx.x * blockDim.x + threadIdx.x;
    const float2* s; __half2* d; int off;
    if (i < NA)                    { s=(const float2*)q;  d=(__half2*)g_qh;  off=i; }
    else if (i < 2*NA)             { s=(const float2*)k;  d=(__half2*)g_kh;  off=i-NA; }
    else if (i < 3*NA)             { s=(const float2*)v;  d=(__half2*)g_vh;  off=i-2*NA; }
    else if (i < 3*NA+NW)          { s=(const float2*)Wq; d=(__half2*)g_wqh; off=i-3*NA; }
    else if (i < 3*NA+2*NW)        { s=(const float2*)Wk; d=(__half2*)g_wkh; off=i-3*NA-NW; }
    else if (i < 3*NA+2*NW+NWV)    { s=(const float2*)Wv; d=(__half2*)g_wvh; off=i-3*NA-2*NW; }
    else return;
    float2 vv = s[off];
    d[off] = __floats2half2_rn(vv.x, vv.y);
}

// ================= K1: Q/K/V projections in ONE kernel =================
__global__ __launch_bounds__(256,2) void k_proj() {
    extern __shared__ char sm[];
    int tid = threadIdx.x, w = tid>>5, lane = tid&31;
    int wm = w>>1, wn = w&1, g = lane>>2, tg = lane&3;
    unsigned smu = (unsigned)__cvta_generic_to_shared(sm);
    int z = blockIdx.z;

    if (z >= 4) {
        if (blockIdx.x != 0) return;
        int b = z - 4, s0 = blockIdx.y * 128;
        const __half* A = g_vh + (size_t)b*SS*DD;

        auto issue = [&](int c){
            int buf = c % 3, k0 = c * 32;
            char* TA = sm + buf*12288;
            char* TB = sm + buf*12288 + 8192;
            #pragma unroll
            for (int i=0;i<2;i++){
                int idx = tid + i*256, row = idx>>2, ch = idx&3;
                cp16(TA + row*64 + ((ch^((row>>1)&3))<<4), A + (size_t)(s0+row)*DD + k0 + ch*8);
            }
            {
                int row = tid>>3, ch = tid&7;
                if (row < 32)
                    cp16(TB + row*128 + ((ch^(row&7))<<4), g_wvh + (size_t)(k0+row)*DKK + ch*8);
            }
        };
        issue(0); CP_COMMIT(); issue(1); CP_COMMIT();

        float c[2][4][4] = {};
        const int NC = DD / 32;
        for (int cc = 0; cc < NC; cc++) {
            CP_WAIT(1);
            __syncthreads();
            if (cc + 2 < NC) issue(cc + 2);
            CP_COMMIT();
            int buf = cc % 3;
            unsigned TAu = smu + buf*12288;
            unsigned TBu = smu + buf*12288 + 8192;
            #pragma unroll
            for (int ks = 0; ks < 2; ks++) {
                unsigned a[2][4];
                #pragma unroll
                for (int mf = 0; mf < 2; mf++) {
                    int row = wm*32 + mf*16 + (lane&15);
                    int ch  = ks*2 + ((lane>>4)&1);
                    ldsm4(a[mf], TAu + row*64 + ((ch^((row>>1)&3))<<4));
                }
                // B frags: 2 x ldsm4t covering nf pairs
                unsigned bf[4][2];
                #pragma unroll
                for (int np = 0; np < 2; np++) {
                    int nc2  = wn*4 + np*2 + ((lane>>4)&1);
                    int krow = ks*16 + (lane&15);
                    unsigned r[4];
                    ldsm4t(r, TBu + krow*128 + ((nc2^(krow&7))<<4));
                    bf[np*2][0]=r[0]; bf[np*2][1]=r[1]; bf[np*2+1][0]=r[2]; bf[np*2+1][1]=r[3];
                }
                #pragma unroll
                for (int mf = 0; mf < 2; mf++)
                    #pragma unroll
                    for (int nf = 0; nf < 4; nf++)
                        mma16816(c[mf][nf], a[mf], bf[nf]);
            }
        }
        __half* C = g_vsh + (size_t)b*SS*DKK;
        #pragma unroll
        for (int mf = 0; mf < 2; mf++) {
            int r = s0 + wm*32 + mf*16 + g;
            #pragma unroll
            for (int nf = 0; nf < 4; nf++) {
                int dk = wn*32 + nf*8 + 2*tg;
                *(__half2*)&C[(size_t)r*DKK + dk]     = __floats2half2_rn(c[mf][nf][0], c[mf][nf][1]);
                *(__half2*)&C[(size_t)(r+8)*DKK + dk] = __floats2half2_rn(c[mf][nf][2], c[mf][nf][3]);
            }
        }
        return;
    }

    int kind = z >> 1, b = z & 1;
    int h0 = blockIdx.x * 2, s0 = blockIdx.y * 128;
    const __half* A = (kind ? g_kh : g_qh) + (size_t)b*SS*DD;
    const __half* W = kind ? g_wkh : g_wqh;
    __half* C      = kind ? g_ks : g_qs;
    float scale    = kind ? 1.f : (1.4426950408889634f / 8.f);

    auto issue = [&](int c){
        int buf = c & 3, k0 = c * 32;
        char* TA = sm + buf*8192;
        char* TB = sm + 32768 + buf*8192;
        #pragma unroll
        for (int i=0;i<2;i++){
            int idx = tid + i*256, row = idx>>2, ch = idx&3;
            cp16(TA + row*64 + ((ch^((row>>1)&3))<<4), A + (size_t)(s0+row)*DD + k0 + ch*8);
        }
        #pragma unroll
        for (int i=0;i<2;i++){
            int idx = tid + i*256, row = idx>>4, ch = idx&15;
            int hh = h0 + (ch>>3);
            cp16(TB + row*256 + ((ch^(row&7))<<4), W + ((size_t)hh*DD + k0 + row)*DKK + (ch&7)*8);
        }
    };
    issue(0); CP_COMMIT(); issue(1); CP_COMMIT(); issue(2); CP_COMMIT();

    float c[2][8][4] = {};
    const int NC = DD / 32;
    for (int cc = 0; cc < NC; cc++) {
        CP_WAIT(2);
        __syncthreads();
        if (cc + 3 < NC) issue(cc + 3);
        CP_COMMIT();
        int buf = cc & 3;
        unsigned TAu = smu + buf*8192;
        unsigned TBu = smu + 32768 + buf*8192;
        #pragma unroll
        for (int ks = 0; ks < 2; ks++) {
            unsigned a[2][4];
            #pragma unroll
            for (int mf = 0; mf < 2; mf++) {
                int row = wm*32 + mf*16 + (lane&15);
                int ch  = ks*2 + ((lane>>4)&1);
                ldsm4(a[mf], TAu + row*64 + ((ch^((row>>1)&3))<<4));
            }
            // B frags: 4 x ldsm4t covering nf pairs (256B rows)
            unsigned bf[8][2];
            #pragma unroll
            for (int np = 0; np < 4; np++) {
                int nc2  = wn*8 + np*2 + ((lane>>4)&1);
                int krow = ks*16 + (lane&15);
                unsigned r[4];
                ldsm4t(r, TBu + krow*256 + ((nc2^(krow&7))<<4));
                bf[np*2][0]=r[0]; bf[np*2][1]=r[1]; bf[np*2+1][0]=r[2]; bf[np*2+1][1]=r[3];
            }
            #pragma unroll
            for (int mf = 0; mf < 2; mf++)
                #pragma unroll
                for (int nf = 0; nf < 8; nf++)
                    mma16816(c[mf][nf], a[mf], bf[nf]);
        }
    }
    int head = h0 + wn;
    #pragma unroll
    for (int mf = 0; mf < 2; mf++) {
        int r = s0 + wm*32 + mf*16 + g;
        #pragma unroll
        for (int nf = 0; nf < 8; nf++) {
            int dk = nf*8 + 2*tg;
            *(__half2*)&C[((size_t)(b*HH+head)*SS + r    )*DKK + dk] =
                __floats2half2_rn(c[mf][nf][0]*scale, c[mf][nf][1]*scale);
            *(__half2*)&C[((size_t)(b*HH+head)*SS + r + 8)*DKK + dk] =
                __floats2half2_rn(c[mf][nf][2]*scale, c[mf][nf][3]*scale);
        }
    }
}

// ================= K2: pass 1 — rowsums, f16-accum MMA, ldsm4 K frags =================
__global__ __launch_bounds__(256,2) void k_rowsum() {
    extern __shared__ char sm[];
    int b = blockIdx.z, h = blockIdx.y;
    int s0 = blockIdx.x * 128;
    int tid = threadIdx.x, w = tid>>5, lane = tid&31;
    int wm = w>>1, wn = w&1, g = lane>>2, tg = lane&3;
    unsigned smu = (unsigned)__cvta_generic_to_shared(sm);
    const __half* Qsrc  = g_qs + ((size_t)(b*HH+h)*SS + s0)*DKK;
    const __half* Kbase = g_ks + ((size_t)(b*HH+h)*SS)*DKK;

    char* TQ = sm;   // 16KB resident
    auto issueK = [&](int c){
        char* TK = sm + 16384 + (c%3)*16384;
        #pragma unroll
        for (int i=0;i<4;i++){
            int idx = tid + i*256, row = idx>>3, ch = idx&7;
            cp16(TK + row*128 + ((ch^(row&7))<<4), Kbase + ((size_t)(c*128+row))*DKK + ch*8);
        }
    };
    #pragma unroll
    for (int i=0;i<4;i++){
        int idx = tid + i*256, row = idx>>3, ch = idx&7;
        cp16(TQ + row*128 + ((ch^(row&7))<<4), Qsrc + (size_t)row*DKK + ch*8);
    }
    issueK(0); CP_COMMIT();
    issueK(1); CP_COMMIT();

    CP_WAIT(1);
    __syncthreads();
    unsigned qa[4][2][4];
    #pragma unroll
    for (int ks = 0; ks < 4; ks++)
        #pragma unroll
        for (int mf = 0; mf < 2; mf++) {
            int row = wm*32 + mf*16 + (lane&15);
            int ch  = ks*2 + ((lane>>4)&1);
            ldsm4(qa[ks][mf], smu + row*128 + ((ch^(row&7))<<4));
        }

    float rs[2][2] = {};
    const int NC = SS / 128;  // 16
    for (int cc = 0; cc < NC; cc++) {
        CP_WAIT(1);
        __syncthreads();
        if (cc + 2 < NC) issueK(cc + 2);
        CP_COMMIT();
        unsigned TKu = smu + 16384 + (cc%3)*16384;
        unsigned c[2][8][2] = {};
        #pragma unroll
        for (int ks = 0; ks < 4; ks++) {
            // K frags: 4 x ldsm4 covering nf pairs
            unsigned bf[8][2];
            #pragma unroll
            for (int np = 0; np < 4; np++) {
                int mIdx = lane >> 3;                      // 0..3
                int nf2  = np*2 + (mIdx >> 1);
                int kh   = mIdx & 1;
                int trow = wn*64 + nf2*8 + (lane&7);
                int ch2  = ks*2 + kh;
                unsigned r[4];
                ldsm4(r, TKu + trow*128 + ((ch2^(trow&7))<<4));
                bf[np*2][0]=r[0]; bf[np*2][1]=r[1]; bf[np*2+1][0]=r[2]; bf[np*2+1][1]=r[3];
            }
            #pragma unroll
            for (int mf = 0; mf < 2; mf++)
                #pragma unroll
                for (int nf = 0; nf < 8; nf++)
                    mma16816h(c[mf][nf], qa[ks][mf], bf[nf]);
        }
        #pragma unroll
        for (int mf = 0; mf < 2; mf++) {
            __half2 e0[8], e1[8];
            #pragma unroll
            for (int nf = 0; nf < 8; nf++) {
                e0[nf] = h2ex2(*reinterpret_cast<__half2*>(&c[mf][nf][0]));
                e1[nf] = h2ex2(*reinterpret_cast<__half2*>(&c[mf][nf][1]));
            }
            #pragma unroll
            for (int st = 4; st >= 1; st >>= 1)
                #pragma unroll
                for (int i = 0; i < st; i++) {
                    e0[i] = __hadd2(e0[i], e0[i+st]);
                    e1[i] = __hadd2(e1[i], e1[i+st]);
                }
            float2 f0 = __half22float2(e0[0]);
            float2 f1 = __half22float2(e1[0]);
            rs[mf][0] += f0.x + f0.y;
            rs[mf][1] += f1.x + f1.y;
        }
    }
    #pragma unroll
    for (int mf = 0; mf < 2; mf++)
        #pragma unroll
        for (int i = 0; i < 2; i++) {
            float s = rs[mf][i];
            s += __shfl_xor_sync(0xffffffffu, s, 1);
            s += __shfl_xor_sync(0xffffffffu, s, 2);
            rs[mf][i] = s;
        }
    float* red = (float*)sm;
    __syncthreads();
    if (tg == 0) {
        #pragma unroll
        for (int mf = 0; mf < 2; mf++)
            #pragma unroll
            for (int i = 0; i < 2; i++)
                red[wn*128 + wm*32 + mf*16 + g + 8*i] = rs[mf][i];
    }
    __syncthreads();
    if (tid < 128) {
        float s = red[tid] + red[128 + tid];
        g_w[(size_t)(b*HH + h)*SS + s0 + tid] = 1.0f / (s * (float)HH);
    }
}

// ================= K3: pass 2 — attn_mean + fused PV, ldsm4 K frags =================
__global__ __launch_bounds__(256,2) void k_attn(float* __restrict__ out) {
    extern __shared__ char sm[];
    int b = blockIdx.z, s0 = blockIdx.y * 128, t0 = blockIdx.x * 64;
    int tid = threadIdx.x, w = tid>>5, lane = tid&31;
    int wm = w>>1, wn = w&1, g = lane>>2, tg = lane&3;
    unsigned smu = (unsigned)__cvta_generic_to_shared(sm);
    char* TV = sm + 73728;

    auto issue = [&](int hh){
        int buf = hh % 3;
        char* TQ = sm + buf*24576;
        char* TK = sm + buf*24576 + 16384;
        const __half* Qsrc = g_qs + ((size_t)(b*HH+hh)*SS + s0)*DKK;
        const __half* Ksrc = g_ks + ((size_t)(b*HH+hh)*SS + t0)*DKK;
        #pragma unroll
        for (int i=0;i<4;i++){
            int idx = tid + i*256, row = idx>>3, ch = idx&7;
            cp16(TQ + row*128 + ((ch^(row&7))<<4), Qsrc + (size_t)row*DKK + ch*8);
        }
        #pragma unroll
        for (int i=0;i<2;i++){
            int idx = tid + i*256, row = idx>>3, ch = idx&7;
            cp16(TK + row*128 + ((ch^(row&7))<<4), Ksrc + (size_t)row*DKK + ch*8);
        }
    };
    {
        const __half* Vsrc = g_vsh + ((size_t)b*SS + t0)*DKK;
        #pragma unroll
        for (int i=0;i<2;i++){
            int idx = tid + i*256, row = idx>>3, ch = idx&7;
            cp16(TV + row*128 + ((ch^(row&7))<<4), Vsrc + (size_t)row*DKK + ch*8);
        }
        issue(0); CP_COMMIT();
        issue(1); CP_COMMIT();
    }

    float wnx[2][2];
    #pragma unroll
    for (int mf = 0; mf < 2; mf++) {
        int r = s0 + wm*32 + mf*16 + g;
        wnx[mf][0] = g_w[(size_t)(b*HH + 0)*SS + r];
        wnx[mf][1] = g_w[(size_t)(b*HH + 0)*SS + r + 8];
    }

    float acc[2][4][4] = {};
    for (int h = 0; h < HH; h++) {
        CP_WAIT(1);
        __syncthreads();
        if (h + 2 < HH) issue(h + 2);
        CP_COMMIT();
        float wc[2][2] = {{wnx[0][0], wnx[0][1]}, {wnx[1][0], wnx[1][1]}};
        if (h + 1 < HH) {
            #pragma unroll
            for (int mf = 0; mf < 2; mf++) {
                int r = s0 + wm*32 + mf*16 + g;
                wnx[mf][0] = g_w[(size_t)(b*HH + h+1)*SS + r];
                wnx[mf][1] = g_w[(size_t)(b*HH + h+1)*SS + r + 8];
            }
        }
        int buf = h % 3;
        unsigned TQu = smu + buf*24576;
        unsigned TKu = smu + buf*24576 + 16384;
        unsigned sc[2][4][2] = {};
        #pragma unroll
        for (int ks = 0; ks < 4; ks++) {
            unsigned a[2][4];
            #pragma unroll
            for (int mf = 0; mf < 2; mf++) {
                int row = wm*32 + mf*16 + (lane&15);
                int ch  = ks*2 + ((lane>>4)&1);
                ldsm4(a[mf], TQu + row*128 + ((ch^(row&7))<<4));
            }
            // K frags: 2 x ldsm4 covering nf pairs
            unsigned bf[4][2];
            #pragma unroll
            for (int np = 0; np < 2; np++) {
                int mIdx = lane >> 3;
                int nf2  = np*2 + (mIdx >> 1);
                int kh   = mIdx & 1;
                int trow = wn*32 + nf2*8 + (lane&7);
                int ch2  = ks*2 + kh;
                unsigned r[4];
                ldsm4(r, TKu + trow*128 + ((ch2^(trow&7))<<4));
                bf[np*2][0]=r[0]; bf[np*2][1]=r[1]; bf[np*2+1][0]=r[2]; bf[np*2+1][1]=r[3];
            }
            #pragma unroll
            for (int mf = 0; mf < 2; mf++)
                #pragma unroll
                for (int nf = 0; nf < 4; nf++)
                    mma16816h(sc[mf][nf], a[mf], bf[nf]);
        }
        #pragma unroll
        for (int mf = 0; mf < 2; mf++)
            #pragma unroll
            for (int nf = 0; nf < 4; nf++) {
                float2 f01 = __half22float2(h2ex2(*reinterpret_cast<__half2*>(&sc[mf][nf][0])));
                float2 f23 = __half22float2(h2ex2(*reinterpret_cast<__half2*>(&sc[mf][nf][1])));
                acc[mf][nf][0] = fmaf(f01.x, wc[mf][0], acc[mf][nf][0]);
                acc[mf][nf][1] = fmaf(f01.y, wc[mf][0], acc[mf][nf][1]);
                acc[mf][nf][2] = fmaf(f23.x, wc[mf][1], acc[mf][nf][2]);
                acc[mf][nf][3] = fmaf(f23.y, wc[mf][1], acc[mf][nf][3]);
            }
    }

    float* AM = out + (size_t)BB*SS*DD + ((size_t)b*SS) * SS;
    #pragma unroll
    for (int mf = 0; mf < 2; mf++) {
        int r = s0 + wm*32 + mf*16 + g;
        #pragma unroll
        for (int nf = 0; nf < 4; nf++) {
            int cc = t0 + wn*32 + nf*8 + 2*tg;
            *(float2*)&AM[(size_t)r * SS + cc]       = make_float2(acc[mf][nf][0], acc[mf][nf][1]);
            *(float2*)&AM[(size_t)(r + 8) * SS + cc] = make_float2(acc[mf][nf][2], acc[mf][nf][3]);
        }
    }

    __syncthreads();
    char* TP = sm;
    #pragma unroll
    for (int mf = 0; mf < 2; mf++) {
        int rl = wm*32 + mf*16 + g;
        #pragma unroll
        for (int nf = 0; nf < 4; nf++) {
            int col = wn*32 + nf*8 + 2*tg;
            int c8 = col >> 3;
            *(__half2*)(TP + rl*128 + ((c8^(rl&7))<<4) + (col&7)*2) =
                __floats2half2_rn(acc[mf][nf][0], acc[mf][nf][1]);
            *(__half2*)(TP + (rl+8)*128 + ((c8^((rl+8)&7))<<4) + (col&7)*2) =
                __floats2half2_rn(acc[mf][nf][2], acc[mf][nf][3]);
        }
    }
    __syncthreads();

    unsigned TPu = smu;
    unsigned TVu = smu + 73728;
    float hacc[2][4][4] = {};
    #pragma unroll
    for (int kc = 0; kc < 4; kc++) {
        unsigned a[2][4];
        #pragma unroll
        for (int mf = 0; mf < 2; mf++) {
            int row = wm*32 + mf*16 + (lane&15);
            int c8 = kc*2 + ((lane>>4)&1);
            ldsm4(a[mf], TPu + row*128 + ((c8^(row&7))<<4));
        }
        // V frags: 2 x ldsm4t covering nf pairs
        unsigned bf[4][2];
        #pragma unroll
        for (int np = 0; np < 2; np++) {
            int nf2  = wn*4 + np*2 + ((lane>>4)&1);
            int trow = kc*16 + (lane&15);
            int ch   = nf2 ^ (trow&7);
            unsigned r[4];
            ldsm4t(r, TVu + trow*128 + (ch<<4));
            bf[np*2][0]=r[0]; bf[np*2][1]=r[1]; bf[np*2+1][0]=r[2]; bf[np*2+1][1]=r[3];
        }
        #pragma unroll
        for (int mf = 0; mf < 2; mf++)
            #pragma unroll
            for (int nf = 0; nf < 4; nf++)
                mma16816(hacc[mf][nf], a[mf], bf[nf]);
    }
    float* C = g_headp + (((size_t)(t0>>6)*BB + b)*SS) * DKK;
    #pragma unroll
    for (int mf = 0; mf < 2; mf++) {
        int r = s0 + wm*32 + mf*16 + g;
        #pragma unroll
        for (int nf = 0; nf < 4; nf++) {
            int dc = wn*32 + nf*8 + 2*tg;
            *(float2*)&C[(size_t)r*DKK + dc]     = make_float2(hacc[mf][nf][0], hacc[mf][nf][1]);
            *(float2*)&C[(size_t)(r+8)*DKK + dc] = make_float2(hacc[mf][nf][2], hacc[mf][nf][3]);
        }
    }
}

// ================= K5: reduce PV partials =================
__global__ void k_reduce() {
    size_t i4 = (size_t)blockIdx.x * blockDim.x + threadIdx.x;
    size_t N4 = (size_t)BB*SS*DKK / 4;
    if (i4 >= N4) return;
    float4 s = make_float4(0.f, 0.f, 0.f, 0.f);
    #pragma unroll
    for (int c = 0; c < KSPLIT; c++) {
        float4 x = *((const float4*)g_headp + (size_t)c * N4 + i4);
        s.x += x.x; s.y += x.y; s.z += x.z; s.w += x.w;
    }
    *((float4*)g_head + i4) = s;
}

// ================= K6: out = head @ Wo =================
__global__ void k_out(const float* __restrict__ Wo, float* __restrict__ out) {
    int d0 = blockIdx.x * 64, r0 = blockIdx.y * 64;
    __shared__ float Hs[64][64];
    __shared__ float Ws[64][64];
    int tid = threadIdx.x, tx = tid & 15, ty = tid >> 4;
    {
        const float* src = g_head + (size_t)r0 * DKK;
        #pragma unroll
        for (int l = 0; l < 4; l++) {
            int f = tid + l * 256, row = f >> 4, c4 = (f & 15) * 4;
            float4 x = *(const float4*)&src[(size_t)row * 64 + c4];
            Hs[c4+0][row] = x.x; Hs[c4+1][row] = x.y;
            Hs[c4+2][row] = x.z; Hs[c4+3][row] = x.w;
        }
    }
    #pragma unroll
    for (int l = 0; l < 4; l++) {
        int f = tid + l * 256, kk = f >> 4, c4 = (f & 15) * 4;
        *(float4*)&Ws[kk][c4] = *(const float4*)&Wo[(size_t)kk * DD + d0 + c4];
    }
    __syncthreads();
    float acc[4][4] = {};
    #pragma unroll 16
    for (int kk = 0; kk < 64; kk++) {
        float4 a  = *(const float4*)&Hs[kk][ty * 4];
        float4 bb = *(const float4*)&Ws[kk][tx * 4];
        float av[4] = {a.x, a.y, a.z, a.w};
        float bv[4] = {bb.x, bb.y, bb.z, bb.w};
        #pragma unroll
        for (int i = 0; i < 4; i++)
            #pragma unroll
            for (int j = 0; j < 4; j++)
                acc[i][j] = fmaf(av[i], bv[j], acc[i][j]);
    }
    #pragma unroll
    for (int i = 0; i < 4; i++) {
        float4 o; o.x = acc[i][0]; o.y = acc[i][1]; o.z = acc[i][2]; o.w = acc[i][3];
        *(float4*)&out[(size_t)(r0 + ty * 4 + i) * DD + d0 + tx * 4] = o;
    }
}

// ================= launch =================
extern "C" void kernel_launch(void* const* d_in, const int* in_sizes, int n_in,
                              void* d_out, int out_size) {
    const float* q  = (const float*)d_in[0];
    const float* k  = (const float*)d_in[1];
    const float* v  = (const float*)d_in[2];
    const float* Wq = (const float*)d_in[3];
    const float* Wk = (const float*)d_in[4];
    const float* Wv = (const float*)d_in[5];
    const float* Wo = (const float*)d_in[6];
    float* out = (float*)d_out;

    int ntot = 3*(BB*SS*DD/2) + 2*(HH*DD*DKK/2) + DD*DKK/2;
    k_cvt_all<<<(ntot + 255)/256, 256>>>(q, k, v, Wq, Wk, Wv);

    const int smem_proj   = 65536;
    const int smem_rowsum = 65536;
    const int smem_attn   = 81920;
    cudaFuncSetAttribute(k_proj,   cudaFuncAttributeMaxDynamicSharedMemorySize, smem_proj);
    cudaFuncSetAttribute(k_rowsum, cudaFuncAttributeMaxDynamicSharedMemorySize, smem_rowsum);
    cudaFuncSetAttribute(k_attn,   cudaFuncAttributeMaxDynamicSharedMemorySize, smem_attn);

    dim3 gp(DD/128, SS/128, 6);
    k_proj<<<gp, 256, smem_proj>>>();

    dim3 gr(SS/128, HH, BB);
    k_rowsum<<<gr, 256, smem_rowsum>>>();

    dim3 ga(SS/64, SS/128, BB);
    k_attn<<<ga, 256, smem_attn>>>(out);

    int n4 = BB*SS*DKK/4;
    k_reduce<<<(n4 + 255)/256, 256>>>();

    dim3 go(DD/64, BB*SS/64);
    k_out<<<go, 256>>>(Wo, out);
}

// round 15
// speedup vs baseline: 1.1111x; 1.1111x over previous
#include <cuda_runtime.h>
#include <cuda_fp16.h>

#define BB 2
#define SS 2048
#define DD 1024
#define HH 16
#define DKK 64
#define KSPLIT 32

// ---------------- device scratch ----------------
__device__ __align__(16) __half g_qh [(size_t)BB*SS*DD];
__device__ __align__(16) __half g_kh [(size_t)BB*SS*DD];
__device__ __align__(16) __half g_vh [(size_t)BB*SS*DD];
__device__ __align__(16) __half g_wqh[(size_t)HH*DD*DKK];
__device__ __align__(16) __half g_wkh[(size_t)HH*DD*DKK];
__device__ __align__(16) __half g_wvh[(size_t)DD*DKK];
__device__ __align__(16) __half g_woh[(size_t)DKK*DD];
__device__ __align__(16) __half g_qs [(size_t)BB*HH*SS*DKK];  // fp16 Q proj, scaled log2e/8
__device__ __align__(16) __half g_ks [(size_t)BB*HH*SS*DKK];  // fp16 K proj
__device__ __align__(16) __half g_vsh[(size_t)BB*SS*DKK];     // fp16 V proj
__device__ float g_w [(size_t)BB*HH*SS];                       // 1/(H * rowsum)
__device__ float g_headp[(size_t)KSPLIT*BB*SS*DKK];            // per-t-tile PV partials
__device__ __align__(16) __half g_headh[(size_t)BB*SS*DKK];    // fp16 reduced head

// ---------------- helpers ----------------
__device__ __forceinline__ __half2 h2ex2(__half2 x){
    unsigned xi = *reinterpret_cast<unsigned*>(&x), yi;
    asm("ex2.approx.f16x2 %0, %1;" : "=r"(yi) : "r"(xi));
    return *reinterpret_cast<__half2*>(&yi);
}
__device__ __forceinline__ void mma16816(float c[4], const unsigned a[4], const unsigned b[2]) {
    asm volatile("mma.sync.aligned.m16n8k16.row.col.f32.f16.f16.f32 "
        "{%0,%1,%2,%3},{%4,%5,%6,%7},{%8,%9},{%0,%1,%2,%3};\n"
        : "+f"(c[0]),"+f"(c[1]),"+f"(c[2]),"+f"(c[3])
        : "r"(a[0]),"r"(a[1]),"r"(a[2]),"r"(a[3]),"r"(b[0]),"r"(b[1]));
}
__device__ __forceinline__ void mma16816h(unsigned c[2], const unsigned a[4], const unsigned b[2]) {
    asm volatile("mma.sync.aligned.m16n8k16.row.col.f16.f16.f16.f16 "
        "{%0,%1},{%2,%3,%4,%5},{%6,%7},{%0,%1};\n"
        : "+r"(c[0]),"+r"(c[1])
        : "r"(a[0]),"r"(a[1]),"r"(a[2]),"r"(a[3]),"r"(b[0]),"r"(b[1]));
}
__device__ __forceinline__ void ldsm4(unsigned r[4], unsigned a) {
    asm volatile("ldmatrix.sync.aligned.m8n8.x4.shared.b16 {%0,%1,%2,%3}, [%4];"
        : "=r"(r[0]),"=r"(r[1]),"=r"(r[2]),"=r"(r[3]) : "r"(a));
}
__device__ __forceinline__ void ldsm2(unsigned r[2], unsigned a) {
    asm volatile("ldmatrix.sync.aligned.m8n8.x2.shared.b16 {%0,%1}, [%2];"
        : "=r"(r[0]),"=r"(r[1]) : "r"(a));
}
__device__ __forceinline__ void ldsm2t(unsigned r[2], unsigned a) {
    asm volatile("ldmatrix.sync.aligned.m8n8.x2.trans.shared.b16 {%0,%1}, [%2];"
        : "=r"(r[0]),"=r"(r[1]) : "r"(a));
}
__device__ __forceinline__ void cp16(void* dst, const void* src) {
    unsigned d = (unsigned)__cvta_generic_to_shared(dst);
    asm volatile("cp.async.ca.shared.global [%0], [%1], 16;\n" :: "r"(d), "l"(src));
}
#define CP_COMMIT() asm volatile("cp.async.commit_group;\n")
#define CP_WAIT(N)  asm volatile("cp.async.wait_group %0;\n" :: "n"(N))

// ================= K0: fused fp32 -> fp16 conversions =================
__global__ void k_cvt_all(const float* __restrict__ q, const float* __restrict__ k,
                          const float* __restrict__ v, const float* __restrict__ Wq,
                          const float* __restrict__ Wk, const float* __restrict__ Wv,
                          const float* __restrict__ Wo) {
    const int NA = BB*SS*DD/2;
    const int NW = HH*DD*DKK/2;
    const int NWV = DD*DKK/2;
    int i = blockIdx.x * blockDim.x + threadIdx.x;
    const float2* s; __half2* d; int off;
    if (i < NA)                      { s=(const float2*)q;  d=(__half2*)g_qh;  off=i; }
    else if (i < 2*NA)               { s=(const float2*)k;  d=(__half2*)g_kh;  off=i-NA; }
    else if (i < 3*NA)               { s=(const float2*)v;  d=(__half2*)g_vh;  off=i-2*NA; }
    else if (i < 3*NA+NW)            { s=(const float2*)Wq; d=(__half2*)g_wqh; off=i-3*NA; }
    else if (i < 3*NA+2*NW)          { s=(const float2*)Wk; d=(__half2*)g_wkh; off=i-3*NA-NW; }
    else if (i < 3*NA+2*NW+NWV)      { s=(const float2*)Wv; d=(__half2*)g_wvh; off=i-3*NA-2*NW; }
    else if (i < 3*NA+2*NW+2*NWV)    { s=(const float2*)Wo; d=(__half2*)g_woh; off=i-3*NA-2*NW-NWV; }
    else return;
    float2 vv = s[off];
    d[off] = __floats2half2_rn(vv.x, vv.y);
}

// ================= K1: Q/K/V projections in ONE kernel =================
__global__ __launch_bounds__(256,2) void k_proj() {
    extern __shared__ char sm[];
    int tid = threadIdx.x, w = tid>>5, lane = tid&31;
    int wm = w>>1, wn = w&1, g = lane>>2, tg = lane&3;
    unsigned smu = (unsigned)__cvta_generic_to_shared(sm);
    int z = blockIdx.z;

    if (z >= 4) {
        if (blockIdx.x != 0) return;
        int b = z - 4, s0 = blockIdx.y * 128;
        const __half* A = g_vh + (size_t)b*SS*DD;

        auto issue = [&](int c){
            int buf = c % 3, k0 = c * 32;
            char* TA = sm + buf*12288;
            char* TB = sm + buf*12288 + 8192;
            #pragma unroll
            for (int i=0;i<2;i++){
                int idx = tid + i*256, row = idx>>2, ch = idx&3;
                cp16(TA + row*64 + ((ch^((row>>1)&3))<<4), A + (size_t)(s0+row)*DD + k0 + ch*8);
            }
            {
                int row = tid>>3, ch = tid&7;
                if (row < 32)
                    cp16(TB + row*128 + ((ch^(row&7))<<4), g_wvh + (size_t)(k0+row)*DKK + ch*8);
            }
        };
        issue(0); CP_COMMIT(); issue(1); CP_COMMIT();

        float c[2][4][4] = {};
        const int NC = DD / 32;
        for (int cc = 0; cc < NC; cc++) {
            CP_WAIT(1);
            __syncthreads();
            if (cc + 2 < NC) issue(cc + 2);
            CP_COMMIT();
            int buf = cc % 3;
            unsigned TAu = smu + buf*12288;
            unsigned TBu = smu + buf*12288 + 8192;
            #pragma unroll
            for (int ks = 0; ks < 2; ks++) {
                unsigned a[2][4];
                #pragma unroll
                for (int mf = 0; mf < 2; mf++) {
                    int row = wm*32 + mf*16 + (lane&15);
                    int ch  = ks*2 + ((lane>>4)&1);
                    ldsm4(a[mf], TAu + row*64 + ((ch^((row>>1)&3))<<4));
                }
                unsigned bf[4][2];
                #pragma unroll
                for (int nf = 0; nf < 4; nf++) {
                    int krow = ks*16 + (lane&15);
                    int nc = wn*4 + nf;
                    ldsm2t(bf[nf], TBu + krow*128 + ((nc^(krow&7))<<4));
                }
                #pragma unroll
                for (int mf = 0; mf < 2; mf++)
                    #pragma unroll
                    for (int nf = 0; nf < 4; nf++)
                        mma16816(c[mf][nf], a[mf], bf[nf]);
            }
        }
        __half* C = g_vsh + (size_t)b*SS*DKK;
        #pragma unroll
        for (int mf = 0; mf < 2; mf++) {
            int r = s0 + wm*32 + mf*16 + g;
            #pragma unroll
            for (int nf = 0; nf < 4; nf++) {
                int dk = wn*32 + nf*8 + 2*tg;
                *(__half2*)&C[(size_t)r*DKK + dk]     = __floats2half2_rn(c[mf][nf][0], c[mf][nf][1]);
                *(__half2*)&C[(size_t)(r+8)*DKK + dk] = __floats2half2_rn(c[mf][nf][2], c[mf][nf][3]);
            }
        }
        return;
    }

    int kind = z >> 1, b = z & 1;
    int h0 = blockIdx.x * 2, s0 = blockIdx.y * 128;
    const __half* A = (kind ? g_kh : g_qh) + (size_t)b*SS*DD;
    const __half* W = kind ? g_wkh : g_wqh;
    __half* C      = kind ? g_ks : g_qs;
    float scale    = kind ? 1.f : (1.4426950408889634f / 8.f);

    auto issue = [&](int c){
        int buf = c & 3, k0 = c * 32;
        char* TA = sm + buf*8192;
        char* TB = sm + 32768 + buf*8192;
        #pragma unroll
        for (int i=0;i<2;i++){
            int idx = tid + i*256, row = idx>>2, ch = idx&3;
            cp16(TA + row*64 + ((ch^((row>>1)&3))<<4), A + (size_t)(s0+row)*DD + k0 + ch*8);
        }
        #pragma unroll
        for (int i=0;i<2;i++){
            int idx = tid + i*256, row = idx>>4, ch = idx&15;
            int hh = h0 + (ch>>3);
            cp16(TB + row*256 + ((ch^(row&7))<<4), W + ((size_t)hh*DD + k0 + row)*DKK + (ch&7)*8);
        }
    };
    issue(0); CP_COMMIT(); issue(1); CP_COMMIT(); issue(2); CP_COMMIT();

    float c[2][8][4] = {};
    const int NC = DD / 32;
    for (int cc = 0; cc < NC; cc++) {
        CP_WAIT(2);
        __syncthreads();
        if (cc + 3 < NC) issue(cc + 3);
        CP_COMMIT();
        int buf = cc & 3;
        unsigned TAu = smu + buf*8192;
        unsigned TBu = smu + 32768 + buf*8192;
        #pragma unroll
        for (int ks = 0; ks < 2; ks++) {
            unsigned a[2][4];
            #pragma unroll
            for (int mf = 0; mf < 2; mf++) {
                int row = wm*32 + mf*16 + (lane&15);
                int ch  = ks*2 + ((lane>>4)&1);
                ldsm4(a[mf], TAu + row*64 + ((ch^((row>>1)&3))<<4));
            }
            unsigned bf[8][2];
            #pragma unroll
            for (int nf = 0; nf < 8; nf++) {
                int krow = ks*16 + (lane&15);
                int nc = wn*8 + nf;
                ldsm2t(bf[nf], TBu + krow*256 + (((nc)^(krow&7))<<4));
            }
            #pragma unroll
            for (int mf = 0; mf < 2; mf++)
                #pragma unroll
                for (int nf = 0; nf < 8; nf++)
                    mma16816(c[mf][nf], a[mf], bf[nf]);
        }
    }
    int head = h0 + wn;
    #pragma unroll
    for (int mf = 0; mf < 2; mf++) {
        int r = s0 + wm*32 + mf*16 + g;
        #pragma unroll
        for (int nf = 0; nf < 8; nf++) {
            int dk = nf*8 + 2*tg;
            *(__half2*)&C[((size_t)(b*HH+head)*SS + r    )*DKK + dk] =
                __floats2half2_rn(c[mf][nf][0]*scale, c[mf][nf][1]*scale);
            *(__half2*)&C[((size_t)(b*HH+head)*SS + r + 8)*DKK + dk] =
                __floats2half2_rn(c[mf][nf][2]*scale, c[mf][nf][3]*scale);
        }
    }
}

// ================= K2: pass 1 — rowsums, f16-accum MMA, Q frags hoisted =================
__global__ __launch_bounds__(256,2) void k_rowsum() {
    extern __shared__ char sm[];
    int b = blockIdx.z, h = blockIdx.y;
    int s0 = blockIdx.x * 128;
    int tid = threadIdx.x, w = tid>>5, lane = tid&31;
    int wm = w>>1, wn = w&1, g = lane>>2, tg = lane&3;
    unsigned smu = (unsigned)__cvta_generic_to_shared(sm);
    const __half* Qsrc  = g_qs + ((size_t)(b*HH+h)*SS + s0)*DKK;
    const __half* Kbase = g_ks + ((size_t)(b*HH+h)*SS)*DKK;

    char* TQ = sm;   // 16KB resident
    auto issueK = [&](int c){
        char* TK = sm + 16384 + (c%3)*16384;
        #pragma unroll
        for (int i=0;i<4;i++){
            int idx = tid + i*256, row = idx>>3, ch = idx&7;
            cp16(TK + row*128 + ((ch^(row&7))<<4), Kbase + ((size_t)(c*128+row))*DKK + ch*8);
        }
    };
    #pragma unroll
    for (int i=0;i<4;i++){
        int idx = tid + i*256, row = idx>>3, ch = idx&7;
        cp16(TQ + row*128 + ((ch^(row&7))<<4), Qsrc + (size_t)row*DKK + ch*8);
    }
    issueK(0); CP_COMMIT();
    issueK(1); CP_COMMIT();

    CP_WAIT(1);
    __syncthreads();
    unsigned qa[4][2][4];
    #pragma unroll
    for (int ks = 0; ks < 4; ks++)
        #pragma unroll
        for (int mf = 0; mf < 2; mf++) {
            int row = wm*32 + mf*16 + (lane&15);
            int ch  = ks*2 + ((lane>>4)&1);
            ldsm4(qa[ks][mf], smu + row*128 + ((ch^(row&7))<<4));
        }

    float rs[2][2] = {};
    const int NC = SS / 128;  // 16
    for (int cc = 0; cc < NC; cc++) {
        CP_WAIT(1);
        __syncthreads();
        if (cc + 2 < NC) issueK(cc + 2);
        CP_COMMIT();
        unsigned TKu = smu + 16384 + (cc%3)*16384;
        unsigned c[2][8][2] = {};
        #pragma unroll
        for (int ks = 0; ks < 4; ks++) {
            unsigned bf[8][2];
            #pragma unroll
            for (int nf = 0; nf < 8; nf++) {
                int trow = wn*64 + nf*8 + (lane&7);
                int ch2  = ks*2 + ((lane>>3)&1);
                ldsm2(bf[nf], TKu + trow*128 + ((ch2^(trow&7))<<4));
            }
            #pragma unroll
            for (int mf = 0; mf < 2; mf++)
                #pragma unroll
                for (int nf = 0; nf < 8; nf++)
                    mma16816h(c[mf][nf], qa[ks][mf], bf[nf]);
        }
        #pragma unroll
        for (int mf = 0; mf < 2; mf++) {
            __half2 e0[8], e1[8];
            #pragma unroll
            for (int nf = 0; nf < 8; nf++) {
                e0[nf] = h2ex2(*reinterpret_cast<__half2*>(&c[mf][nf][0]));
                e1[nf] = h2ex2(*reinterpret_cast<__half2*>(&c[mf][nf][1]));
            }
            #pragma unroll
            for (int st = 4; st >= 1; st >>= 1)
                #pragma unroll
                for (int i = 0; i < st; i++) {
                    e0[i] = __hadd2(e0[i], e0[i+st]);
                    e1[i] = __hadd2(e1[i], e1[i+st]);
                }
            float2 f0 = __half22float2(e0[0]);
            float2 f1 = __half22float2(e1[0]);
            rs[mf][0] += f0.x + f0.y;
            rs[mf][1] += f1.x + f1.y;
        }
    }
    #pragma unroll
    for (int mf = 0; mf < 2; mf++)
        #pragma unroll
        for (int i = 0; i < 2; i++) {
            float s = rs[mf][i];
            s += __shfl_xor_sync(0xffffffffu, s, 1);
            s += __shfl_xor_sync(0xffffffffu, s, 2);
            rs[mf][i] = s;
        }
    float* red = (float*)sm;
    __syncthreads();
    if (tg == 0) {
        #pragma unroll
        for (int mf = 0; mf < 2; mf++)
            #pragma unroll
            for (int i = 0; i < 2; i++)
                red[wn*128 + wm*32 + mf*16 + g + 8*i] = rs[mf][i];
    }
    __syncthreads();
    if (tid < 128) {
        float s = red[tid] + red[128 + tid];
        g_w[(size_t)(b*HH + h)*SS + s0 + tid] = 1.0f / (s * (float)HH);
    }
}

// ================= K3: pass 2 — attn_mean + fused PV, f16-accum scores =================
__global__ __launch_bounds__(256,2) void k_attn(float* __restrict__ out) {
    extern __shared__ char sm[];
    int b = blockIdx.z, s0 = blockIdx.y * 128, t0 = blockIdx.x * 64;
    int tid = threadIdx.x, w = tid>>5, lane = tid&31;
    int wm = w>>1, wn = w&1, g = lane>>2, tg = lane&3;
    unsigned smu = (unsigned)__cvta_generic_to_shared(sm);
    char* TV = sm + 73728;

    auto issue = [&](int hh){
        int buf = hh % 3;
        char* TQ = sm + buf*24576;
        char* TK = sm + buf*24576 + 16384;
        const __half* Qsrc = g_qs + ((size_t)(b*HH+hh)*SS + s0)*DKK;
        const __half* Ksrc = g_ks + ((size_t)(b*HH+hh)*SS + t0)*DKK;
        #pragma unroll
        for (int i=0;i<4;i++){
            int idx = tid + i*256, row = idx>>3, ch = idx&7;
            cp16(TQ + row*128 + ((ch^(row&7))<<4), Qsrc + (size_t)row*DKK + ch*8);
        }
        #pragma unroll
        for (int i=0;i<2;i++){
            int idx = tid + i*256, row = idx>>3, ch = idx&7;
            cp16(TK + row*128 + ((ch^(row&7))<<4), Ksrc + (size_t)row*DKK + ch*8);
        }
    };
    {
        const __half* Vsrc = g_vsh + ((size_t)b*SS + t0)*DKK;
        #pragma unroll
        for (int i=0;i<2;i++){
            int idx = tid + i*256, row = idx>>3, ch = idx&7;
            cp16(TV + row*128 + ((ch^(row&7))<<4), Vsrc + (size_t)row*DKK + ch*8);
        }
        issue(0); CP_COMMIT();
        issue(1); CP_COMMIT();
    }

    float wnx[2][2];
    #pragma unroll
    for (int mf = 0; mf < 2; mf++) {
        int r = s0 + wm*32 + mf*16 + g;
        wnx[mf][0] = g_w[(size_t)(b*HH + 0)*SS + r];
        wnx[mf][1] = g_w[(size_t)(b*HH + 0)*SS + r + 8];
    }

    float acc[2][4][4] = {};
    for (int h = 0; h < HH; h++) {
        CP_WAIT(1);
        __syncthreads();
        if (h + 2 < HH) issue(h + 2);
        CP_COMMIT();
        float wc[2][2] = {{wnx[0][0], wnx[0][1]}, {wnx[1][0], wnx[1][1]}};
        if (h + 1 < HH) {
            #pragma unroll
            for (int mf = 0; mf < 2; mf++) {
                int r = s0 + wm*32 + mf*16 + g;
                wnx[mf][0] = g_w[(size_t)(b*HH + h+1)*SS + r];
                wnx[mf][1] = g_w[(size_t)(b*HH + h+1)*SS + r + 8];
            }
        }
        int buf = h % 3;
        unsigned TQu = smu + buf*24576;
        unsigned TKu = smu + buf*24576 + 16384;
        unsigned sc[2][4][2] = {};
        #pragma unroll
        for (int ks = 0; ks < 4; ks++) {
            unsigned a[2][4];
            #pragma unroll
            for (int mf = 0; mf < 2; mf++) {
                int row = wm*32 + mf*16 + (lane&15);
                int ch  = ks*2 + ((lane>>4)&1);
                ldsm4(a[mf], TQu + row*128 + ((ch^(row&7))<<4));
            }
            unsigned bf[4][2];
            #pragma unroll
            for (int nf = 0; nf < 4; nf++) {
                int trow = wn*32 + nf*8 + (lane&7);
                int ch2  = ks*2 + ((lane>>3)&1);
                ldsm2(bf[nf], TKu + trow*128 + ((ch2^(trow&7))<<4));
            }
            #pragma unroll
            for (int mf = 0; mf < 2; mf++)
                #pragma unroll
                for (int nf = 0; nf < 4; nf++)
                    mma16816h(sc[mf][nf], a[mf], bf[nf]);
        }
        #pragma unroll
        for (int mf = 0; mf < 2; mf++)
            #pragma unroll
            for (int nf = 0; nf < 4; nf++) {
                float2 f01 = __half22float2(h2ex2(*reinterpret_cast<__half2*>(&sc[mf][nf][0])));
                float2 f23 = __half22float2(h2ex2(*reinterpret_cast<__half2*>(&sc[mf][nf][1])));
                acc[mf][nf][0] = fmaf(f01.x, wc[mf][0], acc[mf][nf][0]);
                acc[mf][nf][1] = fmaf(f01.y, wc[mf][0], acc[mf][nf][1]);
                acc[mf][nf][2] = fmaf(f23.x, wc[mf][1], acc[mf][nf][2]);
                acc[mf][nf][3] = fmaf(f23.y, wc[mf][1], acc[mf][nf][3]);
            }
    }

    float* AM = out + (size_t)BB*SS*DD + ((size_t)b*SS) * SS;
    #pragma unroll
    for (int mf = 0; mf < 2; mf++) {
        int r = s0 + wm*32 + mf*16 + g;
        #pragma unroll
        for (int nf = 0; nf < 4; nf++) {
            int cc = t0 + wn*32 + nf*8 + 2*tg;
            *(float2*)&AM[(size_t)r * SS + cc]       = make_float2(acc[mf][nf][0], acc[mf][nf][1]);
            *(float2*)&AM[(size_t)(r + 8) * SS + cc] = make_float2(acc[mf][nf][2], acc[mf][nf][3]);
        }
    }

    __syncthreads();
    char* TP = sm;
    #pragma unroll
    for (int mf = 0; mf < 2; mf++) {
        int rl = wm*32 + mf*16 + g;
        #pragma unroll
        for (int nf = 0; nf < 4; nf++) {
            int col = wn*32 + nf*8 + 2*tg;
            int c8 = col >> 3;
            *(__half2*)(TP + rl*128 + ((c8^(rl&7))<<4) + (col&7)*2) =
                __floats2half2_rn(acc[mf][nf][0], acc[mf][nf][1]);
            *(__half2*)(TP + (rl+8)*128 + ((c8^((rl+8)&7))<<4) + (col&7)*2) =
                __floats2half2_rn(acc[mf][nf][2], acc[mf][nf][3]);
        }
    }
    __syncthreads();

    unsigned TPu = smu;
    unsigned TVu = smu + 73728;
    float hacc[2][4][4] = {};
    #pragma unroll
    for (int kc = 0; kc < 4; kc++) {
        unsigned a[2][4];
        #pragma unroll
        for (int mf = 0; mf < 2; mf++) {
            int row = wm*32 + mf*16 + (lane&15);
            int c8 = kc*2 + ((lane>>4)&1);
            ldsm4(a[mf], TPu + row*128 + ((c8^(row&7))<<4));
        }
        unsigned bf[4][2];
        #pragma unroll
        for (int nf = 0; nf < 4; nf++) {
            int trow = kc*16 + (lane&15);
            int ch = (wn*4 + nf) ^ (trow&7);
            ldsm2t(bf[nf], TVu + trow*128 + (ch<<4));
        }
        #pragma unroll
        for (int mf = 0; mf < 2; mf++)
            #pragma unroll
            for (int nf = 0; nf < 4; nf++)
                mma16816(hacc[mf][nf], a[mf], bf[nf]);
    }
    float* C = g_headp + (((size_t)(t0>>6)*BB + b)*SS) * DKK;
    #pragma unroll
    for (int mf = 0; mf < 2; mf++) {
        int r = s0 + wm*32 + mf*16 + g;
        #pragma unroll
        for (int nf = 0; nf < 4; nf++) {
            int dc = wn*32 + nf*8 + 2*tg;
            *(float2*)&C[(size_t)r*DKK + dc]     = make_float2(hacc[mf][nf][0], hacc[mf][nf][1]);
            *(float2*)&C[(size_t)(r+8)*DKK + dc] = make_float2(hacc[mf][nf][2], hacc[mf][nf][3]);
        }
    }
}

// ================= K5: reduce PV partials -> fp16 head =================
__global__ void k_reduce() {
    size_t i4 = (size_t)blockIdx.x * blockDim.x + threadIdx.x;
    size_t N4 = (size_t)BB*SS*DKK / 4;
    if (i4 >= N4) return;
    float4 s = make_float4(0.f, 0.f, 0.f, 0.f);
    #pragma unroll
    for (int c = 0; c < KSPLIT; c++) {
        float4 x = *((const float4*)g_headp + (size_t)c * N4 + i4);
        s.x += x.x; s.y += x.y; s.z += x.z; s.w += x.w;
    }
    __half2* d = (__half2*)g_headh + i4*2;
    d[0] = __floats2half2_rn(s.x, s.y);
    d[1] = __floats2half2_rn(s.z, s.w);
}

// ================= K6: out = head @ Wo, fp16 MMA (K=64 single shot) =================
// grid: (DD/128, BB*SS/128). smem: A 16K + B 16K = 32K static.
__global__ __launch_bounds__(256,2) void k_out16(float* __restrict__ out) {
    __shared__ __align__(16) char sm[32768];
    int d0 = blockIdx.x * 128, r0 = blockIdx.y * 128;
    int tid = threadIdx.x, w = tid>>5, lane = tid&31;
    int wm = w>>1, wn = w&1, g = lane>>2, tg = lane&3;
    unsigned smu = (unsigned)__cvta_generic_to_shared(sm);
    char* TA = sm;           // head rows 128 x 128B
    char* TB = sm + 16384;   // Wo 64 k-rows x 256B

    #pragma unroll
    for (int i=0;i<4;i++){   // A
        int idx = tid + i*256, row = idx>>3, ch = idx&7;
        cp16(TA + row*128 + ((ch^(row&7))<<4), g_headh + (size_t)(r0+row)*DKK + ch*8);
    }
    #pragma unroll
    for (int i=0;i<4;i++){   // B
        int idx = tid + i*256, krow = idx>>4, ch = idx&15;
        cp16(TB + krow*256 + ((ch^(krow&7))<<4), g_woh + (size_t)krow*DD + d0 + ch*8);
    }
    CP_COMMIT(); CP_WAIT(0);
    __syncthreads();

    float c[2][8][4] = {};
    #pragma unroll
    for (int ks = 0; ks < 4; ks++) {
        unsigned a[2][4];
        #pragma unroll
        for (int mf = 0; mf < 2; mf++) {
            int row = wm*32 + mf*16 + (lane&15);
            int ch  = ks*2 + ((lane>>4)&1);
            ldsm4(a[mf], smu + row*128 + ((ch^(row&7))<<4));
        }
        unsigned bf[8][2];
        #pragma unroll
        for (int nf = 0; nf < 8; nf++) {
            int krow = ks*16 + (lane&15);
            int nc = wn*8 + nf;
            ldsm2t(bf[nf], smu + 16384 + krow*256 + ((nc^(krow&7))<<4));
        }
        #pragma unroll
        for (int mf = 0; mf < 2; mf++)
            #pragma unroll
            for (int nf = 0; nf < 8; nf++)
                mma16816(c[mf][nf], a[mf], bf[nf]);
    }
    #pragma unroll
    for (int mf = 0; mf < 2; mf++) {
        int r = r0 + wm*32 + mf*16 + g;
        #pragma unroll
        for (int nf = 0; nf < 8; nf++) {
            int dc = d0 + wn*64 + nf*8 + 2*tg;
            *(float2*)&out[(size_t)r*DD + dc]     = make_float2(c[mf][nf][0], c[mf][nf][1]);
            *(float2*)&out[(size_t)(r+8)*DD + dc] = make_float2(c[mf][nf][2], c[mf][nf][3]);
        }
    }
}

// ================= launch =================
extern "C" void kernel_launch(void* const* d_in, const int* in_sizes, int n_in,
                              void* d_out, int out_size) {
    const float* q  = (const float*)d_in[0];
    const float* k  = (const float*)d_in[1];
    const float* v  = (const float*)d_in[2];
    const float* Wq = (const float*)d_in[3];
    const float* Wk = (const float*)d_in[4];
    const float* Wv = (const float*)d_in[5];
    const float* Wo = (const float*)d_in[6];
    float* out = (float*)d_out;

    int ntot = 3*(BB*SS*DD/2) + 2*(HH*DD*DKK/2) + 2*(DD*DKK/2);
    k_cvt_all<<<(ntot + 255)/256, 256>>>(q, k, v, Wq, Wk, Wv, Wo);

    const int smem_proj   = 65536;
    const int smem_rowsum = 65536;
    const int smem_attn   = 81920;
    cudaFuncSetAttribute(k_proj,   cudaFuncAttributeMaxDynamicSharedMemorySize, smem_proj);
    cudaFuncSetAttribute(k_rowsum, cudaFuncAttributeMaxDynamicSharedMemorySize, smem_rowsum);
    cudaFuncSetAttribute(k_attn,   cudaFuncAttributeMaxDynamicSharedMemorySize, smem_attn);

    dim3 gp(DD/128, SS/128, 6);
    k_proj<<<gp, 256, smem_proj>>>();

    dim3 gr(SS/128, HH, BB);
    k_rowsum<<<gr, 256, smem_rowsum>>>();

    dim3 ga(SS/64, SS/128, BB);
    k_attn<<<ga, 256, smem_attn>>>(out);

    int n4 = BB*SS*DKK/4;
    k_reduce<<<(n4 + 255)/256, 256>>>();

    dim3 go(DD/128, BB*SS/128);
    k_out16<<<go, 256>>>(out);
}

// round 16
// speedup vs baseline: 1.1321x; 1.0189x over previous
#include <cuda_runtime.h>
#include <cuda_fp16.h>

#define BB 2
#define SS 2048
#define DD 1024
#define HH 16
#define DKK 64
#define KSPLIT 32

// ---------------- device scratch ----------------
__device__ __align__(16) __half g_qh [(size_t)BB*SS*DD];
__device__ __align__(16) __half g_kh [(size_t)BB*SS*DD];
__device__ __align__(16) __half g_vh [(size_t)BB*SS*DD];
__device__ __align__(16) __half g_wqh[(size_t)HH*DD*DKK];
__device__ __align__(16) __half g_wkh[(size_t)HH*DD*DKK];
__device__ __align__(16) __half g_wvh[(size_t)DD*DKK];
__device__ __align__(16) __half g_woh[(size_t)DKK*DD];
__device__ __align__(16) __half g_qs [(size_t)BB*HH*SS*DKK];  // fp16 Q proj, scaled log2e/8
__device__ __align__(16) __half g_ks [(size_t)BB*HH*SS*DKK];  // fp16 K proj
__device__ __align__(16) __half g_vsh[(size_t)BB*SS*DKK];     // fp16 V proj
__device__ float g_w [(size_t)BB*HH*SS];                       // 1/(H * rowsum)
__device__ float g_headp[(size_t)KSPLIT*BB*SS*DKK];            // per-t-tile PV partials
__device__ __align__(16) __half g_headh[(size_t)BB*SS*DKK];    // fp16 reduced head

// ---------------- helpers ----------------
__device__ __forceinline__ __half2 h2ex2(__half2 x){
    unsigned xi = *reinterpret_cast<unsigned*>(&x), yi;
    asm("ex2.approx.f16x2 %0, %1;" : "=r"(yi) : "r"(xi));
    return *reinterpret_cast<__half2*>(&yi);
}
__device__ __forceinline__ void mma16816(float c[4], const unsigned a[4], const unsigned b[2]) {
    asm volatile("mma.sync.aligned.m16n8k16.row.col.f32.f16.f16.f32 "
        "{%0,%1,%2,%3},{%4,%5,%6,%7},{%8,%9},{%0,%1,%2,%3};\n"
        : "+f"(c[0]),"+f"(c[1]),"+f"(c[2]),"+f"(c[3])
        : "r"(a[0]),"r"(a[1]),"r"(a[2]),"r"(a[3]),"r"(b[0]),"r"(b[1]));
}
__device__ __forceinline__ void mma16816h(unsigned c[2], const unsigned a[4], const unsigned b[2]) {
    asm volatile("mma.sync.aligned.m16n8k16.row.col.f16.f16.f16.f16 "
        "{%0,%1},{%2,%3,%4,%5},{%6,%7},{%0,%1};\n"
        : "+r"(c[0]),"+r"(c[1])
        : "r"(a[0]),"r"(a[1]),"r"(a[2]),"r"(a[3]),"r"(b[0]),"r"(b[1]));
}
__device__ __forceinline__ void ldsm4(unsigned r[4], unsigned a) {
    asm volatile("ldmatrix.sync.aligned.m8n8.x4.shared.b16 {%0,%1,%2,%3}, [%4];"
        : "=r"(r[0]),"=r"(r[1]),"=r"(r[2]),"=r"(r[3]) : "r"(a));
}
__device__ __forceinline__ void ldsm2(unsigned r[2], unsigned a) {
    asm volatile("ldmatrix.sync.aligned.m8n8.x2.shared.b16 {%0,%1}, [%2];"
        : "=r"(r[0]),"=r"(r[1]) : "r"(a));
}
__device__ __forceinline__ void ldsm2t(unsigned r[2], unsigned a) {
    asm volatile("ldmatrix.sync.aligned.m8n8.x2.trans.shared.b16 {%0,%1}, [%2];"
        : "=r"(r[0]),"=r"(r[1]) : "r"(a));
}
__device__ __forceinline__ void cp16(void* dst, const void* src) {
    unsigned d = (unsigned)__cvta_generic_to_shared(dst);
    asm volatile("cp.async.ca.shared.global [%0], [%1], 16;\n" :: "r"(d), "l"(src));
}
#define CP_COMMIT() asm volatile("cp.async.commit_group;\n")
#define CP_WAIT(N)  asm volatile("cp.async.wait_group %0;\n" :: "n"(N))

// ================= K0: fused fp32 -> fp16 conversions =================
__global__ void k_cvt_all(const float* __restrict__ q, const float* __restrict__ k,
                          const float* __restrict__ v, const float* __restrict__ Wq,
                          const float* __restrict__ Wk, const float* __restrict__ Wv,
                          const float* __restrict__ Wo) {
    const int NA = BB*SS*DD/2;
    const int NW = HH*DD*DKK/2;
    const int NWV = DD*DKK/2;
    int i = blockIdx.x * blockDim.x + threadIdx.x;
    const float2* s; __half2* d; int off;
    if (i < NA)                      { s=(const float2*)q;  d=(__half2*)g_qh;  off=i; }
    else if (i < 2*NA)               { s=(const float2*)k;  d=(__half2*)g_kh;  off=i-NA; }
    else if (i < 3*NA)               { s=(const float2*)v;  d=(__half2*)g_vh;  off=i-2*NA; }
    else if (i < 3*NA+NW)            { s=(const float2*)Wq; d=(__half2*)g_wqh; off=i-3*NA; }
    else if (i < 3*NA+2*NW)          { s=(const float2*)Wk; d=(__half2*)g_wkh; off=i-3*NA-NW; }
    else if (i < 3*NA+2*NW+NWV)      { s=(const float2*)Wv; d=(__half2*)g_wvh; off=i-3*NA-2*NW; }
    else if (i < 3*NA+2*NW+2*NWV)    { s=(const float2*)Wo; d=(__half2*)g_woh; off=i-3*NA-2*NW-NWV; }
    else return;
    float2 vv = s[off];
    d[off] = __floats2half2_rn(vv.x, vv.y);
}

// ================= K1: Q/K/V projections in ONE kernel =================
// QK path: 64-wide k-chunks, 3-stage ring (3 x 32KB).
__global__ __launch_bounds__(256,2) void k_proj() {
    extern __shared__ char sm[];
    int tid = threadIdx.x, w = tid>>5, lane = tid&31;
    int wm = w>>1, wn = w&1, g = lane>>2, tg = lane&3;
    unsigned smu = (unsigned)__cvta_generic_to_shared(sm);
    int z = blockIdx.z;

    if (z >= 4) {
        if (blockIdx.x != 0) return;
        int b = z - 4, s0 = blockIdx.y * 128;
        const __half* A = g_vh + (size_t)b*SS*DD;

        auto issue = [&](int c){
            int buf = c % 3, k0 = c * 32;
            char* TA = sm + buf*12288;
            char* TB = sm + buf*12288 + 8192;
            #pragma unroll
            for (int i=0;i<2;i++){
                int idx = tid + i*256, row = idx>>2, ch = idx&3;
                cp16(TA + row*64 + ((ch^((row>>1)&3))<<4), A + (size_t)(s0+row)*DD + k0 + ch*8);
            }
            {
                int row = tid>>3, ch = tid&7;
                if (row < 32)
                    cp16(TB + row*128 + ((ch^(row&7))<<4), g_wvh + (size_t)(k0+row)*DKK + ch*8);
            }
        };
        issue(0); CP_COMMIT(); issue(1); CP_COMMIT();

        float c[2][4][4] = {};
        const int NC = DD / 32;
        for (int cc = 0; cc < NC; cc++) {
            CP_WAIT(1);
            __syncthreads();
            if (cc + 2 < NC) issue(cc + 2);
            CP_COMMIT();
            int buf = cc % 3;
            unsigned TAu = smu + buf*12288;
            unsigned TBu = smu + buf*12288 + 8192;
            #pragma unroll
            for (int ks = 0; ks < 2; ks++) {
                unsigned a[2][4];
                #pragma unroll
                for (int mf = 0; mf < 2; mf++) {
                    int row = wm*32 + mf*16 + (lane&15);
                    int ch  = ks*2 + ((lane>>4)&1);
                    ldsm4(a[mf], TAu + row*64 + ((ch^((row>>1)&3))<<4));
                }
                unsigned bf[4][2];
                #pragma unroll
                for (int nf = 0; nf < 4; nf++) {
                    int krow = ks*16 + (lane&15);
                    int nc = wn*4 + nf;
                    ldsm2t(bf[nf], TBu + krow*128 + ((nc^(krow&7))<<4));
                }
                #pragma unroll
                for (int mf = 0; mf < 2; mf++)
                    #pragma unroll
                    for (int nf = 0; nf < 4; nf++)
                        mma16816(c[mf][nf], a[mf], bf[nf]);
            }
        }
        __half* C = g_vsh + (size_t)b*SS*DKK;
        #pragma unroll
        for (int mf = 0; mf < 2; mf++) {
            int r = s0 + wm*32 + mf*16 + g;
            #pragma unroll
            for (int nf = 0; nf < 4; nf++) {
                int dk = wn*32 + nf*8 + 2*tg;
                *(__half2*)&C[(size_t)r*DKK + dk]     = __floats2half2_rn(c[mf][nf][0], c[mf][nf][1]);
                *(__half2*)&C[(size_t)(r+8)*DKK + dk] = __floats2half2_rn(c[mf][nf][2], c[mf][nf][3]);
            }
        }
        return;
    }

    // ---- Q/K projections: 64-wide k-chunks ----
    int kind = z >> 1, b = z & 1;
    int h0 = blockIdx.x * 2, s0 = blockIdx.y * 128;
    const __half* A = (kind ? g_kh : g_qh) + (size_t)b*SS*DD;
    const __half* W = kind ? g_wkh : g_wqh;
    __half* C      = kind ? g_ks : g_qs;
    float scale    = kind ? 1.f : (1.4426950408889634f / 8.f);

    auto issue = [&](int c){
        int buf = c % 3, k0 = c * 64;
        char* TA = sm + buf*32768;
        char* TB = sm + buf*32768 + 16384;
        #pragma unroll
        for (int i=0;i<4;i++){        // A: 128 rows x 64 cols (128B rows)
            int idx = tid + i*256, row = idx>>3, ch = idx&7;
            cp16(TA + row*128 + ((ch^(row&7))<<4), A + (size_t)(s0+row)*DD + k0 + ch*8);
        }
        #pragma unroll
        for (int i=0;i<4;i++){        // B: 64 k-rows x 128 cols (256B rows, 2 heads)
            int idx = tid + i*256, krow = idx>>4, ch = idx&15;
            int hh = h0 + (ch>>3);
            cp16(TB + krow*256 + ((ch^(krow&7))<<4), W + ((size_t)hh*DD + k0 + krow)*DKK + (ch&7)*8);
        }
    };
    issue(0); CP_COMMIT(); issue(1); CP_COMMIT();

    float c[2][8][4] = {};
    const int NC = DD / 64;   // 16
    for (int cc = 0; cc < NC; cc++) {
        CP_WAIT(1);
        __syncthreads();
        if (cc + 2 < NC) issue(cc + 2);
        CP_COMMIT();
        int buf = cc % 3;
        unsigned TAu = smu + buf*32768;
        unsigned TBu = smu + buf*32768 + 16384;
        #pragma unroll
        for (int ks = 0; ks < 4; ks++) {
            unsigned a[2][4];
            #pragma unroll
            for (int mf = 0; mf < 2; mf++) {
                int row = wm*32 + mf*16 + (lane&15);
                int ch  = ks*2 + ((lane>>4)&1);
                ldsm4(a[mf], TAu + row*128 + ((ch^(row&7))<<4));
            }
            unsigned bf[8][2];
            #pragma unroll
            for (int nf = 0; nf < 8; nf++) {
                int krow = ks*16 + (lane&15);
                int nc = wn*8 + nf;
                ldsm2t(bf[nf], TBu + krow*256 + ((nc^(krow&7))<<4));
            }
            #pragma unroll
            for (int mf = 0; mf < 2; mf++)
                #pragma unroll
                for (int nf = 0; nf < 8; nf++)
                    mma16816(c[mf][nf], a[mf], bf[nf]);
        }
    }
    int head = h0 + wn;
    #pragma unroll
    for (int mf = 0; mf < 2; mf++) {
        int r = s0 + wm*32 + mf*16 + g;
        #pragma unroll
        for (int nf = 0; nf < 8; nf++) {
            int dk = nf*8 + 2*tg;
            *(__half2*)&C[((size_t)(b*HH+head)*SS + r    )*DKK + dk] =
                __floats2half2_rn(c[mf][nf][0]*scale, c[mf][nf][1]*scale);
            *(__half2*)&C[((size_t)(b*HH+head)*SS + r + 8)*DKK + dk] =
                __floats2half2_rn(c[mf][nf][2]*scale, c[mf][nf][3]*scale);
        }
    }
}

// ================= K2: pass 1 — rowsums, f16-accum MMA, Q frags hoisted =================
__global__ __launch_bounds__(256,2) void k_rowsum() {
    extern __shared__ char sm[];
    int b = blockIdx.z, h = blockIdx.y;
    int s0 = blockIdx.x * 128;
    int tid = threadIdx.x, w = tid>>5, lane = tid&31;
    int wm = w>>1, wn = w&1, g = lane>>2, tg = lane&3;
    unsigned smu = (unsigned)__cvta_generic_to_shared(sm);
    const __half* Qsrc  = g_qs + ((size_t)(b*HH+h)*SS + s0)*DKK;
    const __half* Kbase = g_ks + ((size_t)(b*HH+h)*SS)*DKK;

    char* TQ = sm;   // 16KB resident
    auto issueK = [&](int c){
        char* TK = sm + 16384 + (c%3)*16384;
        #pragma unroll
        for (int i=0;i<4;i++){
            int idx = tid + i*256, row = idx>>3, ch = idx&7;
            cp16(TK + row*128 + ((ch^(row&7))<<4), Kbase + ((size_t)(c*128+row))*DKK + ch*8);
        }
    };
    #pragma unroll
    for (int i=0;i<4;i++){
        int idx = tid + i*256, row = idx>>3, ch = idx&7;
        cp16(TQ + row*128 + ((ch^(row&7))<<4), Qsrc + (size_t)row*DKK + ch*8);
    }
    issueK(0); CP_COMMIT();
    issueK(1); CP_COMMIT();

    CP_WAIT(1);
    __syncthreads();
    unsigned qa[4][2][4];
    #pragma unroll
    for (int ks = 0; ks < 4; ks++)
        #pragma unroll
        for (int mf = 0; mf < 2; mf++) {
            int row = wm*32 + mf*16 + (lane&15);
            int ch  = ks*2 + ((lane>>4)&1);
            ldsm4(qa[ks][mf], smu + row*128 + ((ch^(row&7))<<4));
        }

    float rs[2][2] = {};
    const int NC = SS / 128;  // 16
    for (int cc = 0; cc < NC; cc++) {
        CP_WAIT(1);
        __syncthreads();
        if (cc + 2 < NC) issueK(cc + 2);
        CP_COMMIT();
        unsigned TKu = smu + 16384 + (cc%3)*16384;
        unsigned c[2][8][2] = {};
        #pragma unroll
        for (int ks = 0; ks < 4; ks++) {
            unsigned bf[8][2];
            #pragma unroll
            for (int nf = 0; nf < 8; nf++) {
                int trow = wn*64 + nf*8 + (lane&7);
                int ch2  = ks*2 + ((lane>>3)&1);
                ldsm2(bf[nf], TKu + trow*128 + ((ch2^(trow&7))<<4));
            }
            #pragma unroll
            for (int mf = 0; mf < 2; mf++)
                #pragma unroll
                for (int nf = 0; nf < 8; nf++)
                    mma16816h(c[mf][nf], qa[ks][mf], bf[nf]);
        }
        #pragma unroll
        for (int mf = 0; mf < 2; mf++) {
            __half2 e0[8], e1[8];
            #pragma unroll
            for (int nf = 0; nf < 8; nf++) {
                e0[nf] = h2ex2(*reinterpret_cast<__half2*>(&c[mf][nf][0]));
                e1[nf] = h2ex2(*reinterpret_cast<__half2*>(&c[mf][nf][1]));
            }
            #pragma unroll
            for (int st = 4; st >= 1; st >>= 1)
                #pragma unroll
                for (int i = 0; i < st; i++) {
                    e0[i] = __hadd2(e0[i], e0[i+st]);
                    e1[i] = __hadd2(e1[i], e1[i+st]);
                }
            float2 f0 = __half22float2(e0[0]);
            float2 f1 = __half22float2(e1[0]);
            rs[mf][0] += f0.x + f0.y;
            rs[mf][1] += f1.x + f1.y;
        }
    }
    #pragma unroll
    for (int mf = 0; mf < 2; mf++)
        #pragma unroll
        for (int i = 0; i < 2; i++) {
            float s = rs[mf][i];
            s += __shfl_xor_sync(0xffffffffu, s, 1);
            s += __shfl_xor_sync(0xffffffffu, s, 2);
            rs[mf][i] = s;
        }
    float* red = (float*)sm;
    __syncthreads();
    if (tg == 0) {
        #pragma unroll
        for (int mf = 0; mf < 2; mf++)
            #pragma unroll
            for (int i = 0; i < 2; i++)
                red[wn*128 + wm*32 + mf*16 + g + 8*i] = rs[mf][i];
    }
    __syncthreads();
    if (tid < 128) {
        float s = red[tid] + red[128 + tid];
        g_w[(size_t)(b*HH + h)*SS + s0 + tid] = 1.0f / (s * (float)HH);
    }
}

// ================= K3: pass 2 — attn_mean + fused PV, f16-accum scores =================
__global__ __launch_bounds__(256,2) void k_attn(float* __restrict__ out) {
    extern __shared__ char sm[];
    int b = blockIdx.z, s0 = blockIdx.y * 128, t0 = blockIdx.x * 64;
    int tid = threadIdx.x, w = tid>>5, lane = tid&31;
    int wm = w>>1, wn = w&1, g = lane>>2, tg = lane&3;
    unsigned smu = (unsigned)__cvta_generic_to_shared(sm);
    char* TV = sm + 73728;

    auto issue = [&](int hh){
        int buf = hh % 3;
        char* TQ = sm + buf*24576;
        char* TK = sm + buf*24576 + 16384;
        const __half* Qsrc = g_qs + ((size_t)(b*HH+hh)*SS + s0)*DKK;
        const __half* Ksrc = g_ks + ((size_t)(b*HH+hh)*SS + t0)*DKK;
        #pragma unroll
        for (int i=0;i<4;i++){
            int idx = tid + i*256, row = idx>>3, ch = idx&7;
            cp16(TQ + row*128 + ((ch^(row&7))<<4), Qsrc + (size_t)row*DKK + ch*8);
        }
        #pragma unroll
        for (int i=0;i<2;i++){
            int idx = tid + i*256, row = idx>>3, ch = idx&7;
            cp16(TK + row*128 + ((ch^(row&7))<<4), Ksrc + (size_t)row*DKK + ch*8);
        }
    };
    {
        const __half* Vsrc = g_vsh + ((size_t)b*SS + t0)*DKK;
        #pragma unroll
        for (int i=0;i<2;i++){
            int idx = tid + i*256, row = idx>>3, ch = idx&7;
            cp16(TV + row*128 + ((ch^(row&7))<<4), Vsrc + (size_t)row*DKK + ch*8);
        }
        issue(0); CP_COMMIT();
        issue(1); CP_COMMIT();
    }

    float wnx[2][2];
    #pragma unroll
    for (int mf = 0; mf < 2; mf++) {
        int r = s0 + wm*32 + mf*16 + g;
        wnx[mf][0] = g_w[(size_t)(b*HH + 0)*SS + r];
        wnx[mf][1] = g_w[(size_t)(b*HH + 0)*SS + r + 8];
    }

    float acc[2][4][4] = {};
    for (int h = 0; h < HH; h++) {
        CP_WAIT(1);
        __syncthreads();
        if (h + 2 < HH) issue(h + 2);
        CP_COMMIT();
        float wc[2][2] = {{wnx[0][0], wnx[0][1]}, {wnx[1][0], wnx[1][1]}};
        if (h + 1 < HH) {
            #pragma unroll
            for (int mf = 0; mf < 2; mf++) {
                int r = s0 + wm*32 + mf*16 + g;
                wnx[mf][0] = g_w[(size_t)(b*HH + h+1)*SS + r];
                wnx[mf][1] = g_w[(size_t)(b*HH + h+1)*SS + r + 8];
            }
        }
        int buf = h % 3;
        unsigned TQu = smu + buf*24576;
        unsigned TKu = smu + buf*24576 + 16384;
        unsigned sc[2][4][2] = {};
        #pragma unroll
        for (int ks = 0; ks < 4; ks++) {
            unsigned a[2][4];
            #pragma unroll
            for (int mf = 0; mf < 2; mf++) {
                int row = wm*32 + mf*16 + (lane&15);
                int ch  = ks*2 + ((lane>>4)&1);
                ldsm4(a[mf], TQu + row*128 + ((ch^(row&7))<<4));
            }
            unsigned bf[4][2];
            #pragma unroll
            for (int nf = 0; nf < 4; nf++) {
                int trow = wn*32 + nf*8 + (lane&7);
                int ch2  = ks*2 + ((lane>>3)&1);
                ldsm2(bf[nf], TKu + trow*128 + ((ch2^(trow&7))<<4));
            }
            #pragma unroll
            for (int mf = 0; mf < 2; mf++)
                #pragma unroll
                for (int nf = 0; nf < 4; nf++)
                    mma16816h(sc[mf][nf], a[mf], bf[nf]);
        }
        #pragma unroll
        for (int mf = 0; mf < 2; mf++)
            #pragma unroll
            for (int nf = 0; nf < 4; nf++) {
                float2 f01 = __half22float2(h2ex2(*reinterpret_cast<__half2*>(&sc[mf][nf][0])));
                float2 f23 = __half22float2(h2ex2(*reinterpret_cast<__half2*>(&sc[mf][nf][1])));
                acc[mf][nf][0] = fmaf(f01.x, wc[mf][0], acc[mf][nf][0]);
                acc[mf][nf][1] = fmaf(f01.y, wc[mf][0], acc[mf][nf][1]);
                acc[mf][nf][2] = fmaf(f23.x, wc[mf][1], acc[mf][nf][2]);
                acc[mf][nf][3] = fmaf(f23.y, wc[mf][1], acc[mf][nf][3]);
            }
    }

    float* AM = out + (size_t)BB*SS*DD + ((size_t)b*SS) * SS;
    #pragma unroll
    for (int mf = 0; mf < 2; mf++) {
        int r = s0 + wm*32 + mf*16 + g;
        #pragma unroll
        for (int nf = 0; nf < 4; nf++) {
            int cc = t0 + wn*32 + nf*8 + 2*tg;
            *(float2*)&AM[(size_t)r * SS + cc]       = make_float2(acc[mf][nf][0], acc[mf][nf][1]);
            *(float2*)&AM[(size_t)(r + 8) * SS + cc] = make_float2(acc[mf][nf][2], acc[mf][nf][3]);
        }
    }

    __syncthreads();
    char* TP = sm;
    #pragma unroll
    for (int mf = 0; mf < 2; mf++) {
        int rl = wm*32 + mf*16 + g;
        #pragma unroll
        for (int nf = 0; nf < 4; nf++) {
            int col = wn*32 + nf*8 + 2*tg;
            int c8 = col >> 3;
            *(__half2*)(TP + rl*128 + ((c8^(rl&7))<<4) + (col&7)*2) =
                __floats2half2_rn(acc[mf][nf][0], acc[mf][nf][1]);
            *(__half2*)(TP + (rl+8)*128 + ((c8^((rl+8)&7))<<4) + (col&7)*2) =
                __floats2half2_rn(acc[mf][nf][2], acc[mf][nf][3]);
        }
    }
    __syncthreads();

    unsigned TPu = smu;
    unsigned TVu = smu + 73728;
    float hacc[2][4][4] = {};
    #pragma unroll
    for (int kc = 0; kc < 4; kc++) {
        unsigned a[2][4];
        #pragma unroll
        for (int mf = 0; mf < 2; mf++) {
            int row = wm*32 + mf*16 + (lane&15);
            int c8 = kc*2 + ((lane>>4)&1);
            ldsm4(a[mf], TPu + row*128 + ((c8^(row&7))<<4));
        }
        unsigned bf[4][2];
        #pragma unroll
        for (int nf = 0; nf < 4; nf++) {
            int trow = kc*16 + (lane&15);
            int ch = (wn*4 + nf) ^ (trow&7);
            ldsm2t(bf[nf], TVu + trow*128 + (ch<<4));
        }
        #pragma unroll
        for (int mf = 0; mf < 2; mf++)
            #pragma unroll
            for (int nf = 0; nf < 4; nf++)
                mma16816(hacc[mf][nf], a[mf], bf[nf]);
    }
    float* C = g_headp + (((size_t)(t0>>6)*BB + b)*SS) * DKK;
    #pragma unroll
    for (int mf = 0; mf < 2; mf++) {
        int r = s0 + wm*32 + mf*16 + g;
        #pragma unroll
        for (int nf = 0; nf < 4; nf++) {
            int dc = wn*32 + nf*8 + 2*tg;
            *(float2*)&C[(size_t)r*DKK + dc]     = make_float2(hacc[mf][nf][0], hacc[mf][nf][1]);
            *(float2*)&C[(size_t)(r+8)*DKK + dc] = make_float2(hacc[mf][nf][2], hacc[mf][nf][3]);
        }
    }
}

// ================= K5: reduce PV partials -> fp16 head =================
__global__ void k_reduce() {
    size_t i4 = (size_t)blockIdx.x * blockDim.x + threadIdx.x;
    size_t N4 = (size_t)BB*SS*DKK / 4;
    if (i4 >= N4) return;
    float4 s = make_float4(0.f, 0.f, 0.f, 0.f);
    #pragma unroll
    for (int c = 0; c < KSPLIT; c++) {
        float4 x = *((const float4*)g_headp + (size_t)c * N4 + i4);
        s.x += x.x; s.y += x.y; s.z += x.z; s.w += x.w;
    }
    __half2* d = (__half2*)g_headh + i4*2;
    d[0] = __floats2half2_rn(s.x, s.y);
    d[1] = __floats2half2_rn(s.z, s.w);
}

// ================= K6: out = head @ Wo, fp16 MMA (K=64 single shot) =================
__global__ __launch_bounds__(256,2) void k_out16(float* __restrict__ out) {
    __shared__ __align__(16) char sm[32768];
    int d0 = blockIdx.x * 128, r0 = blockIdx.y * 128;
    int tid = threadIdx.x, w = tid>>5, lane = tid&31;
    int wm = w>>1, wn = w&1, g = lane>>2, tg = lane&3;
    unsigned smu = (unsigned)__cvta_generic_to_shared(sm);
    char* TA = sm;
    char* TB = sm + 16384;

    #pragma unroll
    for (int i=0;i<4;i++){
        int idx = tid + i*256, row = idx>>3, ch = idx&7;
        cp16(TA + row*128 + ((ch^(row&7))<<4), g_headh + (size_t)(r0+row)*DKK + ch*8);
    }
    #pragma unroll
    for (int i=0;i<4;i++){
        int idx = tid + i*256, krow = idx>>4, ch = idx&15;
        cp16(TB + krow*256 + ((ch^(krow&7))<<4), g_woh + (size_t)krow*DD + d0 + ch*8);
    }
    CP_COMMIT(); CP_WAIT(0);
    __syncthreads();

    float c[2][8][4] = {};
    #pragma unroll
    for (int ks = 0; ks < 4; ks++) {
        unsigned a[2][4];
        #pragma unroll
        for (int mf = 0; mf < 2; mf++) {
            int row = wm*32 + mf*16 + (lane&15);
            int ch  = ks*2 + ((lane>>4)&1);
            ldsm4(a[mf], smu + row*128 + ((ch^(row&7))<<4));
        }
        unsigned bf[8][2];
        #pragma unroll
        for (int nf = 0; nf < 8; nf++) {
            int krow = ks*16 + (lane&15);
            int nc = wn*8 + nf;
            ldsm2t(bf[nf], smu + 16384 + krow*256 + ((nc^(krow&7))<<4));
        }
        #pragma unroll
        for (int mf = 0; mf < 2; mf++)
            #pragma unroll
            for (int nf = 0; nf < 8; nf++)
                mma16816(c[mf][nf], a[mf], bf[nf]);
    }
    #pragma unroll
    for (int mf = 0; mf < 2; mf++) {
        int r = r0 + wm*32 + mf*16 + g;
        #pragma unroll
        for (int nf = 0; nf < 8; nf++) {
            int dc = d0 + wn*64 + nf*8 + 2*tg;
            *(float2*)&out[(size_t)r*DD + dc]     = make_float2(c[mf][nf][0], c[mf][nf][1]);
            *(float2*)&out[(size_t)(r+8)*DD + dc] = make_float2(c[mf][nf][2], c[mf][nf][3]);
        }
    }
}

// ================= launch =================
extern "C" void kernel_launch(void* const* d_in, const int* in_sizes, int n_in,
                              void* d_out, int out_size) {
    const float* q  = (const float*)d_in[0];
    const float* k  = (const float*)d_in[1];
    const float* v  = (const float*)d_in[2];
    const float* Wq = (const float*)d_in[3];
    const float* Wk = (const float*)d_in[4];
    const float* Wv = (const float*)d_in[5];
    const float* Wo = (const float*)d_in[6];
    float* out = (float*)d_out;

    int ntot = 3*(BB*SS*DD/2) + 2*(HH*DD*DKK/2) + 2*(DD*DKK/2);
    k_cvt_all<<<(ntot + 255)/256, 256>>>(q, k, v, Wq, Wk, Wv, Wo);

    const int smem_proj   = 98304;   // QK: 3 x 32KB; V path: 3 x 12KB
    const int smem_rowsum = 65536;
    const int smem_attn   = 81920;
    cudaFuncSetAttribute(k_proj,   cudaFuncAttributeMaxDynamicSharedMemorySize, smem_proj);
    cudaFuncSetAttribute(k_rowsum, cudaFuncAttributeMaxDynamicSharedMemorySize, smem_rowsum);
    cudaFuncSetAttribute(k_attn,   cudaFuncAttributeMaxDynamicSharedMemorySize, smem_attn);

    dim3 gp(DD/128, SS/128, 6);
    k_proj<<<gp, 256, smem_proj>>>();

    dim3 gr(SS/128, HH, BB);
    k_rowsum<<<gr, 256, smem_rowsum>>>();

    dim3 ga(SS/64, SS/128, BB);
    k_attn<<<ga, 256, smem_attn>>>(out);

    int n4 = BB*SS*DKK/4;
    k_reduce<<<(n4 + 255)/256, 256>>>();

    dim3 go(DD/128, BB*SS/128);
    k_out16<<<go, 256>>>(out);
}

// round 17
// speedup vs baseline: 1.1724x; 1.0356x over previous
#include <cuda_runtime.h>
#include <cuda_fp16.h>

#define BB 2
#define SS 2048
#define DD 1024
#define HH 16
#define DKK 64
#define KSPLIT 32

// ---------------- device scratch ----------------
__device__ __align__(16) __half g_qh [(size_t)BB*SS*DD];
__device__ __align__(16) __half g_kh [(size_t)BB*SS*DD];
__device__ __align__(16) __half g_vh [(size_t)BB*SS*DD];
__device__ __align__(16) __half g_wqh[(size_t)HH*DD*DKK];
__device__ __align__(16) __half g_wkh[(size_t)HH*DD*DKK];
__device__ __align__(16) __half g_wvh[(size_t)DD*DKK];
__device__ __align__(16) __half g_woh[(size_t)DKK*DD];
__device__ __align__(16) __half g_qs [(size_t)BB*HH*SS*DKK];  // fp16 Q proj, scaled log2e/8
__device__ __align__(16) __half g_ks [(size_t)BB*HH*SS*DKK];  // fp16 K proj
__device__ __align__(16) __half g_vsh[(size_t)BB*SS*DKK];     // fp16 V proj
__device__ float g_w [(size_t)BB*HH*SS];                       // 1/(H * rowsum)
__device__ __align__(16) __half g_headph[(size_t)KSPLIT*BB*SS*DKK]; // fp16 PV partials
__device__ __align__(16) __half g_headh[(size_t)BB*SS*DKK];    // fp16 reduced head

// ---------------- helpers ----------------
__device__ __forceinline__ __half2 h2ex2(__half2 x){
    unsigned xi = *reinterpret_cast<unsigned*>(&x), yi;
    asm("ex2.approx.f16x2 %0, %1;" : "=r"(yi) : "r"(xi));
    return *reinterpret_cast<__half2*>(&yi);
}
__device__ __forceinline__ void mma16816(float c[4], const unsigned a[4], const unsigned b[2]) {
    asm volatile("mma.sync.aligned.m16n8k16.row.col.f32.f16.f16.f32 "
        "{%0,%1,%2,%3},{%4,%5,%6,%7},{%8,%9},{%0,%1,%2,%3};\n"
        : "+f"(c[0]),"+f"(c[1]),"+f"(c[2]),"+f"(c[3])
        : "r"(a[0]),"r"(a[1]),"r"(a[2]),"r"(a[3]),"r"(b[0]),"r"(b[1]));
}
__device__ __forceinline__ void mma16816h(unsigned c[2], const unsigned a[4], const unsigned b[2]) {
    asm volatile("mma.sync.aligned.m16n8k16.row.col.f16.f16.f16.f16 "
        "{%0,%1},{%2,%3,%4,%5},{%6,%7},{%0,%1};\n"
        : "+r"(c[0]),"+r"(c[1])
        : "r"(a[0]),"r"(a[1]),"r"(a[2]),"r"(a[3]),"r"(b[0]),"r"(b[1]));
}
__device__ __forceinline__ void ldsm4(unsigned r[4], unsigned a) {
    asm volatile("ldmatrix.sync.aligned.m8n8.x4.shared.b16 {%0,%1,%2,%3}, [%4];"
        : "=r"(r[0]),"=r"(r[1]),"=r"(r[2]),"=r"(r[3]) : "r"(a));
}
__device__ __forceinline__ void ldsm2(unsigned r[2], unsigned a) {
    asm volatile("ldmatrix.sync.aligned.m8n8.x2.shared.b16 {%0,%1}, [%2];"
        : "=r"(r[0]),"=r"(r[1]) : "r"(a));
}
__device__ __forceinline__ void ldsm2t(unsigned r[2], unsigned a) {
    asm volatile("ldmatrix.sync.aligned.m8n8.x2.trans.shared.b16 {%0,%1}, [%2];"
        : "=r"(r[0]),"=r"(r[1]) : "r"(a));
}
__device__ __forceinline__ void cp16(void* dst, const void* src) {
    unsigned d = (unsigned)__cvta_generic_to_shared(dst);
    asm volatile("cp.async.ca.shared.global [%0], [%1], 16;\n" :: "r"(d), "l"(src));
}
#define CP_COMMIT() asm volatile("cp.async.commit_group;\n")
#define CP_WAIT(N)  asm volatile("cp.async.wait_group %0;\n" :: "n"(N))

// ================= K0: fused fp32 -> fp16 conversions (float4 vectorized) =================
// processes 4 floats (1 float4 -> 2 half2) per index; grid-stride
__global__ void k_cvt_all(const float* __restrict__ q, const float* __restrict__ k,
                          const float* __restrict__ v, const float* __restrict__ Wq,
                          const float* __restrict__ Wk, const float* __restrict__ Wv,
                          const float* __restrict__ Wo) {
    const int NA = BB*SS*DD/4;          // float4 units per activation tensor
    const int NW = HH*DD*DKK/4;
    const int NWV = DD*DKK/4;
    const int NTOT = 3*NA + 2*NW + 2*NWV;
    for (int i = blockIdx.x * blockDim.x + threadIdx.x; i < NTOT; i += gridDim.x * blockDim.x) {
        const float4* s; __half2* d; int off;
        if (i < NA)                      { s=(const float4*)q;  d=(__half2*)g_qh;  off=i; }
        else if (i < 2*NA)               { s=(const float4*)k;  d=(__half2*)g_kh;  off=i-NA; }
        else if (i < 3*NA)               { s=(const float4*)v;  d=(__half2*)g_vh;  off=i-2*NA; }
        else if (i < 3*NA+NW)            { s=(const float4*)Wq; d=(__half2*)g_wqh; off=i-3*NA; }
        else if (i < 3*NA+2*NW)          { s=(const float4*)Wk; d=(__half2*)g_wkh; off=i-3*NA-NW; }
        else if (i < 3*NA+2*NW+NWV)      { s=(const float4*)Wv; d=(__half2*)g_wvh; off=i-3*NA-2*NW; }
        else                             { s=(const float4*)Wo; d=(__half2*)g_woh; off=i-3*NA-2*NW-NWV; }
        float4 vv = s[off];
        __half2 h0 = __floats2half2_rn(vv.x, vv.y);
        __half2 h1 = __floats2half2_rn(vv.z, vv.w);
        *(unsigned long long*)&d[off*2] =
            ((unsigned long long)*(unsigned*)&h1 << 32) | *(unsigned*)&h0;
    }
}

// ================= K1: Q/K/V projections in ONE kernel =================
__global__ __launch_bounds__(256,2) void k_proj() {
    extern __shared__ char sm[];
    int tid = threadIdx.x, w = tid>>5, lane = tid&31;
    int wm = w>>1, wn = w&1, g = lane>>2, tg = lane&3;
    unsigned smu = (unsigned)__cvta_generic_to_shared(sm);
    int z = blockIdx.z;

    if (z >= 4) {
        if (blockIdx.x != 0) return;
        int b = z - 4, s0 = blockIdx.y * 128;
        const __half* A = g_vh + (size_t)b*SS*DD;

        auto issue = [&](int c){
            int buf = c % 3, k0 = c * 32;
            char* TA = sm + buf*12288;
            char* TB = sm + buf*12288 + 8192;
            #pragma unroll
            for (int i=0;i<2;i++){
                int idx = tid + i*256, row = idx>>2, ch = idx&3;
                cp16(TA + row*64 + ((ch^((row>>1)&3))<<4), A + (size_t)(s0+row)*DD + k0 + ch*8);
            }
            {
                int row = tid>>3, ch = tid&7;
                if (row < 32)
                    cp16(TB + row*128 + ((ch^(row&7))<<4), g_wvh + (size_t)(k0+row)*DKK + ch*8);
            }
        };
        issue(0); CP_COMMIT(); issue(1); CP_COMMIT();

        float c[2][4][4] = {};
        const int NC = DD / 32;
        for (int cc = 0; cc < NC; cc++) {
            CP_WAIT(1);
            __syncthreads();
            if (cc + 2 < NC) issue(cc + 2);
            CP_COMMIT();
            int buf = cc % 3;
            unsigned TAu = smu + buf*12288;
            unsigned TBu = smu + buf*12288 + 8192;
            #pragma unroll
            for (int ks = 0; ks < 2; ks++) {
                unsigned a[2][4];
                #pragma unroll
                for (int mf = 0; mf < 2; mf++) {
                    int row = wm*32 + mf*16 + (lane&15);
                    int ch  = ks*2 + ((lane>>4)&1);
                    ldsm4(a[mf], TAu + row*64 + ((ch^((row>>1)&3))<<4));
                }
                unsigned bf[4][2];
                #pragma unroll
                for (int nf = 0; nf < 4; nf++) {
                    int krow = ks*16 + (lane&15);
                    int nc = wn*4 + nf;
                    ldsm2t(bf[nf], TBu + krow*128 + ((nc^(krow&7))<<4));
                }
                #pragma unroll
                for (int mf = 0; mf < 2; mf++)
                    #pragma unroll
                    for (int nf = 0; nf < 4; nf++)
                        mma16816(c[mf][nf], a[mf], bf[nf]);
            }
        }
        __half* C = g_vsh + (size_t)b*SS*DKK;
        #pragma unroll
        for (int mf = 0; mf < 2; mf++) {
            int r = s0 + wm*32 + mf*16 + g;
            #pragma unroll
            for (int nf = 0; nf < 4; nf++) {
                int dk = wn*32 + nf*8 + 2*tg;
                *(__half2*)&C[(size_t)r*DKK + dk]     = __floats2half2_rn(c[mf][nf][0], c[mf][nf][1]);
                *(__half2*)&C[(size_t)(r+8)*DKK + dk] = __floats2half2_rn(c[mf][nf][2], c[mf][nf][3]);
            }
        }
        return;
    }

    int kind = z >> 1, b = z & 1;
    int h0 = blockIdx.x * 2, s0 = blockIdx.y * 128;
    const __half* A = (kind ? g_kh : g_qh) + (size_t)b*SS*DD;
    const __half* W = kind ? g_wkh : g_wqh;
    __half* C      = kind ? g_ks : g_qs;
    float scale    = kind ? 1.f : (1.4426950408889634f / 8.f);

    auto issue = [&](int c){
        int buf = c % 3, k0 = c * 64;
        char* TA = sm + buf*32768;
        char* TB = sm + buf*32768 + 16384;
        #pragma unroll
        for (int i=0;i<4;i++){
            int idx = tid + i*256, row = idx>>3, ch = idx&7;
            cp16(TA + row*128 + ((ch^(row&7))<<4), A + (size_t)(s0+row)*DD + k0 + ch*8);
        }
        #pragma unroll
        for (int i=0;i<4;i++){
            int idx = tid + i*256, krow = idx>>4, ch = idx&15;
            int hh = h0 + (ch>>3);
            cp16(TB + krow*256 + ((ch^(krow&7))<<4), W + ((size_t)hh*DD + k0 + krow)*DKK + (ch&7)*8);
        }
    };
    issue(0); CP_COMMIT(); issue(1); CP_COMMIT();

    float c[2][8][4] = {};
    const int NC = DD / 64;
    for (int cc = 0; cc < NC; cc++) {
        CP_WAIT(1);
        __syncthreads();
        if (cc + 2 < NC) issue(cc + 2);
        CP_COMMIT();
        int buf = cc % 3;
        unsigned TAu = smu + buf*32768;
        unsigned TBu = smu + buf*32768 + 16384;
        #pragma unroll
        for (int ks = 0; ks < 4; ks++) {
            unsigned a[2][4];
            #pragma unroll
            for (int mf = 0; mf < 2; mf++) {
                int row = wm*32 + mf*16 + (lane&15);
                int ch  = ks*2 + ((lane>>4)&1);
                ldsm4(a[mf], TAu + row*128 + ((ch^(row&7))<<4));
            }
            unsigned bf[8][2];
            #pragma unroll
            for (int nf = 0; nf < 8; nf++) {
                int krow = ks*16 + (lane&15);
                int nc = wn*8 + nf;
                ldsm2t(bf[nf], TBu + krow*256 + ((nc^(krow&7))<<4));
            }
            #pragma unroll
            for (int mf = 0; mf < 2; mf++)
                #pragma unroll
                for (int nf = 0; nf < 8; nf++)
                    mma16816(c[mf][nf], a[mf], bf[nf]);
        }
    }
    int head = h0 + wn;
    #pragma unroll
    for (int mf = 0; mf < 2; mf++) {
        int r = s0 + wm*32 + mf*16 + g;
        #pragma unroll
        for (int nf = 0; nf < 8; nf++) {
            int dk = nf*8 + 2*tg;
            *(__half2*)&C[((size_t)(b*HH+head)*SS + r    )*DKK + dk] =
                __floats2half2_rn(c[mf][nf][0]*scale, c[mf][nf][1]*scale);
            *(__half2*)&C[((size_t)(b*HH+head)*SS + r + 8)*DKK + dk] =
                __floats2half2_rn(c[mf][nf][2]*scale, c[mf][nf][3]*scale);
        }
    }
}

// ================= K2: pass 1 — rowsums, f16-accum MMA, Q frags hoisted =================
__global__ __launch_bounds__(256,2) void k_rowsum() {
    extern __shared__ char sm[];
    int b = blockIdx.z, h = blockIdx.y;
    int s0 = blockIdx.x * 128;
    int tid = threadIdx.x, w = tid>>5, lane = tid&31;
    int wm = w>>1, wn = w&1, g = lane>>2, tg = lane&3;
    unsigned smu = (unsigned)__cvta_generic_to_shared(sm);
    const __half* Qsrc  = g_qs + ((size_t)(b*HH+h)*SS + s0)*DKK;
    const __half* Kbase = g_ks + ((size_t)(b*HH+h)*SS)*DKK;

    char* TQ = sm;
    auto issueK = [&](int c){
        char* TK = sm + 16384 + (c%3)*16384;
        #pragma unroll
        for (int i=0;i<4;i++){
            int idx = tid + i*256, row = idx>>3, ch = idx&7;
            cp16(TK + row*128 + ((ch^(row&7))<<4), Kbase + ((size_t)(c*128+row))*DKK + ch*8);
        }
    };
    #pragma unroll
    for (int i=0;i<4;i++){
        int idx = tid + i*256, row = idx>>3, ch = idx&7;
        cp16(TQ + row*128 + ((ch^(row&7))<<4), Qsrc + (size_t)row*DKK + ch*8);
    }
    issueK(0); CP_COMMIT();
    issueK(1); CP_COMMIT();

    CP_WAIT(1);
    __syncthreads();
    unsigned qa[4][2][4];
    #pragma unroll
    for (int ks = 0; ks < 4; ks++)
        #pragma unroll
        for (int mf = 0; mf < 2; mf++) {
            int row = wm*32 + mf*16 + (lane&15);
            int ch  = ks*2 + ((lane>>4)&1);
            ldsm4(qa[ks][mf], smu + row*128 + ((ch^(row&7))<<4));
        }

    float rs[2][2] = {};
    const int NC = SS / 128;
    for (int cc = 0; cc < NC; cc++) {
        CP_WAIT(1);
        __syncthreads();
        if (cc + 2 < NC) issueK(cc + 2);
        CP_COMMIT();
        unsigned TKu = smu + 16384 + (cc%3)*16384;
        unsigned c[2][8][2] = {};
        #pragma unroll
        for (int ks = 0; ks < 4; ks++) {
            unsigned bf[8][2];
            #pragma unroll
            for (int nf = 0; nf < 8; nf++) {
                int trow = wn*64 + nf*8 + (lane&7);
                int ch2  = ks*2 + ((lane>>3)&1);
                ldsm2(bf[nf], TKu + trow*128 + ((ch2^(trow&7))<<4));
            }
            #pragma unroll
            for (int mf = 0; mf < 2; mf++)
                #pragma unroll
                for (int nf = 0; nf < 8; nf++)
                    mma16816h(c[mf][nf], qa[ks][mf], bf[nf]);
        }
        #pragma unroll
        for (int mf = 0; mf < 2; mf++) {
            __half2 e0[8], e1[8];
            #pragma unroll
            for (int nf = 0; nf < 8; nf++) {
                e0[nf] = h2ex2(*reinterpret_cast<__half2*>(&c[mf][nf][0]));
                e1[nf] = h2ex2(*reinterpret_cast<__half2*>(&c[mf][nf][1]));
            }
            #pragma unroll
            for (int st = 4; st >= 1; st >>= 1)
                #pragma unroll
                for (int i = 0; i < st; i++) {
                    e0[i] = __hadd2(e0[i], e0[i+st]);
                    e1[i] = __hadd2(e1[i], e1[i+st]);
                }
            float2 f0 = __half22float2(e0[0]);
            float2 f1 = __half22float2(e1[0]);
            rs[mf][0] += f0.x + f0.y;
            rs[mf][1] += f1.x + f1.y;
        }
    }
    #pragma unroll
    for (int mf = 0; mf < 2; mf++)
        #pragma unroll
        for (int i = 0; i < 2; i++) {
            float s = rs[mf][i];
            s += __shfl_xor_sync(0xffffffffu, s, 1);
            s += __shfl_xor_sync(0xffffffffu, s, 2);
            rs[mf][i] = s;
        }
    float* red = (float*)sm;
    __syncthreads();
    if (tg == 0) {
        #pragma unroll
        for (int mf = 0; mf < 2; mf++)
            #pragma unroll
            for (int i = 0; i < 2; i++)
                red[wn*128 + wm*32 + mf*16 + g + 8*i] = rs[mf][i];
    }
    __syncthreads();
    if (tid < 128) {
        float s = red[tid] + red[128 + tid];
        g_w[(size_t)(b*HH + h)*SS + s0 + tid] = 1.0f / (s * (float)HH);
    }
}

// ================= K3: pass 2 — attn_mean + fused PV (fp16 partials) =================
__global__ __launch_bounds__(256,2) void k_attn(float* __restrict__ out) {
    extern __shared__ char sm[];
    int b = blockIdx.z, s0 = blockIdx.y * 128, t0 = blockIdx.x * 64;
    int tid = threadIdx.x, w = tid>>5, lane = tid&31;
    int wm = w>>1, wn = w&1, g = lane>>2, tg = lane&3;
    unsigned smu = (unsigned)__cvta_generic_to_shared(sm);
    char* TV = sm + 73728;

    auto issue = [&](int hh){
        int buf = hh % 3;
        char* TQ = sm + buf*24576;
        char* TK = sm + buf*24576 + 16384;
        const __half* Qsrc = g_qs + ((size_t)(b*HH+hh)*SS + s0)*DKK;
        const __half* Ksrc = g_ks + ((size_t)(b*HH+hh)*SS + t0)*DKK;
        #pragma unroll
        for (int i=0;i<4;i++){
            int idx = tid + i*256, row = idx>>3, ch = idx&7;
            cp16(TQ + row*128 + ((ch^(row&7))<<4), Qsrc + (size_t)row*DKK + ch*8);
        }
        #pragma unroll
        for (int i=0;i<2;i++){
            int idx = tid + i*256, row = idx>>3, ch = idx&7;
            cp16(TK + row*128 + ((ch^(row&7))<<4), Ksrc + (size_t)row*DKK + ch*8);
        }
    };
    {
        const __half* Vsrc = g_vsh + ((size_t)b*SS + t0)*DKK;
        #pragma unroll
        for (int i=0;i<2;i++){
            int idx = tid + i*256, row = idx>>3, ch = idx&7;
            cp16(TV + row*128 + ((ch^(row&7))<<4), Vsrc + (size_t)row*DKK + ch*8);
        }
        issue(0); CP_COMMIT();
        issue(1); CP_COMMIT();
    }

    float wnx[2][2];
    #pragma unroll
    for (int mf = 0; mf < 2; mf++) {
        int r = s0 + wm*32 + mf*16 + g;
        wnx[mf][0] = g_w[(size_t)(b*HH + 0)*SS + r];
        wnx[mf][1] = g_w[(size_t)(b*HH + 0)*SS + r + 8];
    }

    float acc[2][4][4] = {};
    for (int h = 0; h < HH; h++) {
        CP_WAIT(1);
        __syncthreads();
        if (h + 2 < HH) issue(h + 2);
        CP_COMMIT();
        float wc[2][2] = {{wnx[0][0], wnx[0][1]}, {wnx[1][0], wnx[1][1]}};
        if (h + 1 < HH) {
            #pragma unroll
            for (int mf = 0; mf < 2; mf++) {
                int r = s0 + wm*32 + mf*16 + g;
                wnx[mf][0] = g_w[(size_t)(b*HH + h+1)*SS + r];
                wnx[mf][1] = g_w[(size_t)(b*HH + h+1)*SS + r + 8];
            }
        }
        int buf = h % 3;
        unsigned TQu = smu + buf*24576;
        unsigned TKu = smu + buf*24576 + 16384;
        unsigned sc[2][4][2] = {};
        #pragma unroll
        for (int ks = 0; ks < 4; ks++) {
            unsigned a[2][4];
            #pragma unroll
            for (int mf = 0; mf < 2; mf++) {
                int row = wm*32 + mf*16 + (lane&15);
                int ch  = ks*2 + ((lane>>4)&1);
                ldsm4(a[mf], TQu + row*128 + ((ch^(row&7))<<4));
            }
            unsigned bf[4][2];
            #pragma unroll
            for (int nf = 0; nf < 4; nf++) {
                int trow = wn*32 + nf*8 + (lane&7);
                int ch2  = ks*2 + ((lane>>3)&1);
                ldsm2(bf[nf], TKu + trow*128 + ((ch2^(trow&7))<<4));
            }
            #pragma unroll
            for (int mf = 0; mf < 2; mf++)
                #pragma unroll
                for (int nf = 0; nf < 4; nf++)
                    mma16816h(sc[mf][nf], a[mf], bf[nf]);
        }
        #pragma unroll
        for (int mf = 0; mf < 2; mf++)
            #pragma unroll
            for (int nf = 0; nf < 4; nf++) {
                float2 f01 = __half22float2(h2ex2(*reinterpret_cast<__half2*>(&sc[mf][nf][0])));
                float2 f23 = __half22float2(h2ex2(*reinterpret_cast<__half2*>(&sc[mf][nf][1])));
                acc[mf][nf][0] = fmaf(f01.x, wc[mf][0], acc[mf][nf][0]);
                acc[mf][nf][1] = fmaf(f01.y, wc[mf][0], acc[mf][nf][1]);
                acc[mf][nf][2] = fmaf(f23.x, wc[mf][1], acc[mf][nf][2]);
                acc[mf][nf][3] = fmaf(f23.y, wc[mf][1], acc[mf][nf][3]);
            }
    }

    float* AM = out + (size_t)BB*SS*DD + ((size_t)b*SS) * SS;
    #pragma unroll
    for (int mf = 0; mf < 2; mf++) {
        int r = s0 + wm*32 + mf*16 + g;
        #pragma unroll
        for (int nf = 0; nf < 4; nf++) {
            int cc = t0 + wn*32 + nf*8 + 2*tg;
            __stcs((float2*)&AM[(size_t)r * SS + cc],       make_float2(acc[mf][nf][0], acc[mf][nf][1]));
            __stcs((float2*)&AM[(size_t)(r + 8) * SS + cc], make_float2(acc[mf][nf][2], acc[mf][nf][3]));
        }
    }

    __syncthreads();
    char* TP = sm;
    #pragma unroll
    for (int mf = 0; mf < 2; mf++) {
        int rl = wm*32 + mf*16 + g;
        #pragma unroll
        for (int nf = 0; nf < 4; nf++) {
            int col = wn*32 + nf*8 + 2*tg;
            int c8 = col >> 3;
            *(__half2*)(TP + rl*128 + ((c8^(rl&7))<<4) + (col&7)*2) =
                __floats2half2_rn(acc[mf][nf][0], acc[mf][nf][1]);
            *(__half2*)(TP + (rl+8)*128 + ((c8^((rl+8)&7))<<4) + (col&7)*2) =
                __floats2half2_rn(acc[mf][nf][2], acc[mf][nf][3]);
        }
    }
    __syncthreads();

    unsigned TPu = smu;
    unsigned TVu = smu + 73728;
    float hacc[2][4][4] = {};
    #pragma unroll
    for (int kc = 0; kc < 4; kc++) {
        unsigned a[2][4];
        #pragma unroll
        for (int mf = 0; mf < 2; mf++) {
            int row = wm*32 + mf*16 + (lane&15);
            int c8 = kc*2 + ((lane>>4)&1);
            ldsm4(a[mf], TPu + row*128 + ((c8^(row&7))<<4));
        }
        unsigned bf[4][2];
        #pragma unroll
        for (int nf = 0; nf < 4; nf++) {
            int trow = kc*16 + (lane&15);
            int ch = (wn*4 + nf) ^ (trow&7);
            ldsm2t(bf[nf], TVu + trow*128 + (ch<<4));
        }
        #pragma unroll
        for (int mf = 0; mf < 2; mf++)
            #pragma unroll
            for (int nf = 0; nf < 4; nf++)
                mma16816(hacc[mf][nf], a[mf], bf[nf]);
    }
    __half* C = g_headph + (((size_t)(t0>>6)*BB + b)*SS) * DKK;
    #pragma unroll
    for (int mf = 0; mf < 2; mf++) {
        int r = s0 + wm*32 + mf*16 + g;
        #pragma unroll
        for (int nf = 0; nf < 4; nf++) {
            int dc = wn*32 + nf*8 + 2*tg;
            *(__half2*)&C[(size_t)r*DKK + dc]     = __floats2half2_rn(hacc[mf][nf][0], hacc[mf][nf][1]);
            *(__half2*)&C[(size_t)(r+8)*DKK + dc] = __floats2half2_rn(hacc[mf][nf][2], hacc[mf][nf][3]);
        }
    }
}

// ================= K5: reduce fp16 PV partials -> fp16 head =================
__global__ void k_reduce() {
    size_t i4 = (size_t)blockIdx.x * blockDim.x + threadIdx.x;   // 8-half chunks
    size_t N4 = (size_t)BB*SS*DKK / 8;
    if (i4 >= N4) return;
    float s[8] = {};
    #pragma unroll
    for (int c = 0; c < KSPLIT; c++) {
        const __half2* x = (const __half2*)((const uint4*)g_headph + (size_t)c * N4 + i4);
        #pragma unroll
        for (int j = 0; j < 4; j++) {
            float2 f = __half22float2(x[j]);
            s[2*j] += f.x; s[2*j+1] += f.y;
        }
    }
    __half2 o[4];
    #pragma unroll
    for (int j = 0; j < 4; j++) o[j] = __floats2half2_rn(s[2*j], s[2*j+1]);
    *((uint4*)g_headh + i4) = *(uint4*)o;
}

// ================= K6: out = head @ Wo, fp16 MMA (K=64 single shot) =================
__global__ __launch_bounds__(256,2) void k_out16(float* __restrict__ out) {
    __shared__ __align__(16) char sm[32768];
    int d0 = blockIdx.x * 128, r0 = blockIdx.y * 128;
    int tid = threadIdx.x, w = tid>>5, lane = tid&31;
    int wm = w>>1, wn = w&1, g = lane>>2, tg = lane&3;
    unsigned smu = (unsigned)__cvta_generic_to_shared(sm);
    char* TA = sm;
    char* TB = sm + 16384;

    #pragma unroll
    for (int i=0;i<4;i++){
        int idx = tid + i*256, row = idx>>3, ch = idx&7;
        cp16(TA + row*128 + ((ch^(row&7))<<4), g_headh + (size_t)(r0+row)*DKK + ch*8);
    }
    #pragma unroll
    for (int i=0;i<4;i++){
        int idx = tid + i*256, krow = idx>>4, ch = idx&15;
        cp16(TB + krow*256 + ((ch^(krow&7))<<4), g_woh + (size_t)krow*DD + d0 + ch*8);
    }
    CP_COMMIT(); CP_WAIT(0);
    __syncthreads();

    float c[2][8][4] = {};
    #pragma unroll
    for (int ks = 0; ks < 4; ks++) {
        unsigned a[2][4];
        #pragma unroll
        for (int mf = 0; mf < 2; mf++) {
            int row = wm*32 + mf*16 + (lane&15);
            int ch  = ks*2 + ((lane>>4)&1);
            ldsm4(a[mf], smu + row*128 + ((ch^(row&7))<<4));
        }
        unsigned bf[8][2];
        #pragma unroll
        for (int nf = 0; nf < 8; nf++) {
            int krow = ks*16 + (lane&15);
            int nc = wn*8 + nf;
            ldsm2t(bf[nf], smu + 16384 + krow*256 + ((nc^(krow&7))<<4));
        }
        #pragma unroll
        for (int mf = 0; mf < 2; mf++)
            #pragma unroll
            for (int nf = 0; nf < 8; nf++)
                mma16816(c[mf][nf], a[mf], bf[nf]);
    }
    #pragma unroll
    for (int mf = 0; mf < 2; mf++) {
        int r = r0 + wm*32 + mf*16 + g;
        #pragma unroll
        for (int nf = 0; nf < 8; nf++) {
            int dc = d0 + wn*64 + nf*8 + 2*tg;
            *(float2*)&out[(size_t)r*DD + dc]     = make_float2(c[mf][nf][0], c[mf][nf][1]);
            *(float2*)&out[(size_t)(r+8)*DD + dc] = make_float2(c[mf][nf][2], c[mf][nf][3]);
        }
    }
}

// ================= launch =================
extern "C" void kernel_launch(void* const* d_in, const int* in_sizes, int n_in,
                              void* d_out, int out_size) {
    const float* q  = (const float*)d_in[0];
    const float* k  = (const float*)d_in[1];
    const float* v  = (const float*)d_in[2];
    const float* Wq = (const float*)d_in[3];
    const float* Wk = (const float*)d_in[4];
    const float* Wv = (const float*)d_in[5];
    const float* Wo = (const float*)d_in[6];
    float* out = (float*)d_out;

    k_cvt_all<<<1184, 256>>>(q, k, v, Wq, Wk, Wv, Wo);   // ~2 iters/thread grid-stride

    const int smem_proj   = 98304;
    const int smem_rowsum = 65536;
    const int smem_attn   = 81920;
    cudaFuncSetAttribute(k_proj,   cudaFuncAttributeMaxDynamicSharedMemorySize, smem_proj);
    cudaFuncSetAttribute(k_rowsum, cudaFuncAttributeMaxDynamicSharedMemorySize, smem_rowsum);
    cudaFuncSetAttribute(k_attn,   cudaFuncAttributeMaxDynamicSharedMemorySize, smem_attn);

    dim3 gp(DD/128, SS/128, 6);
    k_proj<<<gp, 256, smem_proj>>>();

    dim3 gr(SS/128, HH, BB);
    k_rowsum<<<gr, 256, smem_rowsum>>>();

    dim3 ga(SS/64, SS/128, BB);
    k_attn<<<ga, 256, smem_attn>>>(out);

    int n8 = BB*SS*DKK/8;
    k_reduce<<<(n8 + 255)/256, 256>>>();

    dim3 go(DD/128, BB*SS/128);
    k_out16<<<go, 256>>>(out);
}